// round 7
// baseline (speedup 1.0000x reference)
#include <cuda_runtime.h>
#include <cuda_fp16.h>
#include <cstdint>

// Problem dims (fixed by the reference)
#define QN   512
#define CN   512
#define TNT  128
#define DIN  512
#define DHD  256
#define KCORR (TNT * DHD)   // 32768
#define MAXLAG 4
#define NLAG  9             // lags -4..4
#define MROWS (QN * TNT)    // 65536

// ---------------------------------------------------------------------------
// Scratch (static device globals; no allocation allowed)
// ---------------------------------------------------------------------------
__device__ __half g_Hh [MROWS * DHD];   // hidden hi (reused audio/video)
__device__ __half g_Hl [MROWS * DHD];   // hidden lo
__device__ __half g_Ahf[MROWS * DHD];   // audio hi  [Q, T*DH]
__device__ __half g_Alf[MROWS * DHD];   // audio lo
__device__ __half g_Phf[MROWS * DHD];   // video hi  [C, T*DH]
__device__ __half g_Plf[MROWS * DHD];   // video lo
__device__ float g_Wc[DHD * DHD];       // folded v_w2 @ W (fp32)
__device__ float g_bc[DHD];             // folded v_b2 @ W
// pre-split, pre-transposed weights: [N][K], K contiguous (fp16 hi/lo)
__device__ __half g_W1ah[DHD * DIN], g_W1al[DHD * DIN];
__device__ __half g_W1vh[DHD * DIN], g_W1vl[DHD * DIN];
__device__ __half g_W2ah[DHD * DHD], g_W2al[DHD * DHD];
__device__ __half g_Wcth[DHD * DHD], g_Wctl[DHD * DHD];
__device__ float g_S [NLAG * QN * CN];  // per-lag scores

// ---------------------------------------------------------------------------
// Portable PTX helpers (valid on compute_103 virtual target)
// ---------------------------------------------------------------------------
__device__ __forceinline__ uint32_t smem_u32(const void* p) {
    uint32_t a;
    asm("{ .reg .u64 t; cvta.to.shared.u64 t, %1; cvt.u32.u64 %0, t; }"
        : "=r"(a) : "l"(p));
    return a;
}

#define CP_ASYNC_16(dst, src) \
    asm volatile("cp.async.ca.shared.global [%0], [%1], 16;" \
        :: "r"(dst), "l"(src) : "memory")
#define CP_ASYNC_CG_16(dst, src) \
    asm volatile("cp.async.cg.shared.global [%0], [%1], 16;" \
        :: "r"(dst), "l"(src) : "memory")
#define CP_ASYNC_COMMIT() asm volatile("cp.async.commit_group;" ::: "memory")
#define CP_ASYNC_WAIT_2() asm volatile("cp.async.wait_group 2;" ::: "memory")
#define CP_ASYNC_WAIT_1() asm volatile("cp.async.wait_group 1;" ::: "memory")
#define CP_ASYNC_WAIT_0() asm volatile("cp.async.wait_group 0;" ::: "memory")

#define LDSM_X4(r, addr) \
    asm volatile("ldmatrix.sync.aligned.m8n8.x4.shared.b16 {%0,%1,%2,%3}, [%4];" \
        : "=r"((r)[0]), "=r"((r)[1]), "=r"((r)[2]), "=r"((r)[3]) : "r"(addr))

__device__ __forceinline__ void mma_f16(float* c, const uint32_t* a,
                                        const uint32_t* b) {
    asm volatile(
        "mma.sync.aligned.m16n8k16.row.col.f32.f16.f16.f32 "
        "{%0,%1,%2,%3}, {%4,%5,%6,%7}, {%8,%9}, {%0,%1,%2,%3};"
        : "+f"(c[0]), "+f"(c[1]), "+f"(c[2]), "+f"(c[3])
        : "r"(a[0]), "r"(a[1]), "r"(a[2]), "r"(a[3]), "r"(b[0]), "r"(b[1]));
}

// ---------------------------------------------------------------------------
// Prep: fold v_w2 @ W -> g_Wc, g_bc
// ---------------------------------------------------------------------------
__global__ void prep_w_kernel(const float* __restrict__ v_w2,
                              const float* __restrict__ v_b2,
                              const float* __restrict__ W) {
    int i = blockIdx.x;
    int j = threadIdx.x;
    float acc = 0.f;
    #pragma unroll 8
    for (int k = 0; k < DHD; ++k)
        acc += v_w2[i * DHD + k] * W[k * DHD + j];
    g_Wc[i * DHD + j] = acc;
    if (i == 0) {
        float accb = 0.f;
        #pragma unroll 8
        for (int k = 0; k < DHD; ++k)
            accb += v_b2[k] * W[k * DHD + j];
        g_bc[j] = accb;
    }
}

// Prep: transpose + split fp32 [K, 256] -> fp16 hi/lo [256][K]
__global__ void split_t_kernel(const float* __restrict__ in,
                               __half* __restrict__ oh,
                               __half* __restrict__ ol, int K) {
    int n = blockIdx.x;
    for (int k = threadIdx.x; k < K; k += blockDim.x) {
        float v = in[(size_t)k * DHD + n];
        __half h = __float2half_rn(v);
        __half l = __float2half_rn(v - __half2float(h));
        oh[(size_t)n * K + k] = h;
        ol[(size_t)n * K + k] = l;
    }
}

// ---------------------------------------------------------------------------
// MLP tiling constants
// ---------------------------------------------------------------------------
#define BKC     32                  // K elems per chunk (MLP)
#define ROWB    80                  // padded row stride bytes (64 data + 16)
#define TILE_PB (128 * ROWB)        // 10240
#define BUF_PB  (4 * TILE_PB)       // Ah, Al, Bh, Bl
#define HMMA_SMEM (2 * BUF_PB)      // 81920

extern __shared__ char dsm[];

// ---------------------------------------------------------------------------
// MLP GEMM on HMMA (fp16 3-term split). 256 threads, 128x128 tile.
// ---------------------------------------------------------------------------
template <bool CONVERT_A, bool RELU>
__global__ __launch_bounds__(256, 1)
void mlp_hmma_kernel(const float* __restrict__ Af,
                     const __half* __restrict__ Ahg,
                     const __half* __restrict__ Alg,
                     const __half* __restrict__ Bh,
                     const __half* __restrict__ Bl,
                     const float* __restrict__ bias,
                     __half* __restrict__ Oh,
                     __half* __restrict__ Ol,
                     int K) {
    const uint32_t sb = smem_u32(dsm);
    const int tid  = threadIdx.x;
    const int wid  = tid >> 5;
    const int lane = tid & 31;
    const int bm = blockIdx.x * 128;
    const int bn = blockIdx.y * 128;
    const int NCH = K / BKC;

    const int wm = (wid >> 2) * 64;
    const int wn = (wid & 3) * 32;

    float acc[4][4][4];
    #pragma unroll
    for (int mi = 0; mi < 4; ++mi)
        #pragma unroll
        for (int nf = 0; nf < 4; ++nf)
            #pragma unroll
            for (int r = 0; r < 4; ++r) acc[mi][nf][r] = 0.f;

    const int aRow = wm + (lane & 15);
    const int aSeg = (lane >> 4) << 4;
    const int bg   = lane >> 3;
    const int bRow = wn + ((bg >> 1) << 3) + (lane & 7);
    const int bSeg = (bg & 1) << 4;

    float4 areg[4];

    auto prefetch_B = [&](int c, int buf) {
        const int k0 = c * BKC;
        const uint32_t base = sb + buf * BUF_PB;
        #pragma unroll
        for (int i = 0; i < 4; ++i) {
            int u = tid + i * 256;
            int tile = 2 + (u >> 9);
            int w = u & 511;
            int row = w >> 2, seg = w & 3;
            uint32_t dst = base + tile * TILE_PB + row * ROWB + seg * 16;
            const __half* src =
                ((u >> 9) == 0 ? Bh : Bl) + (size_t)(bn + row) * K + k0 + seg * 8;
            CP_ASYNC_16(dst, src);
        }
    };
    auto prefetch_A_f16 = [&](int c, int buf) {
        const int k0 = c * BKC;
        const uint32_t base = sb + buf * BUF_PB;
        #pragma unroll
        for (int i = 0; i < 4; ++i) {
            int u = tid + i * 256;
            int tile = u >> 9;
            int w = u & 511;
            int row = w >> 2, seg = w & 3;
            uint32_t dst = base + tile * TILE_PB + row * ROWB + seg * 16;
            const __half* src =
                (tile == 0 ? Ahg : Alg) + (size_t)(bm + row) * K + k0 + seg * 8;
            CP_ASYNC_16(dst, src);
        }
    };
    auto ldg_A_f32 = [&](int c) {
        const int k0 = c * BKC;
        #pragma unroll
        for (int i = 0; i < 4; ++i) {
            int s = tid + i * 256;
            int row = s >> 3, seg = s & 7;
            areg[i] = *(const float4*)&Af[(size_t)(bm + row) * K + k0 + seg * 4];
        }
    };
    auto sts_A_split = [&](int buf) {
        const uint32_t base = sb + buf * BUF_PB;
        #pragma unroll
        for (int i = 0; i < 4; ++i) {
            int s = tid + i * 256;
            int row = s >> 3, seg = s & 7;
            uint32_t off = row * ROWB + seg * 8;
            float4 v = areg[i];
            __half hx = __float2half_rn(v.x);
            __half hy = __float2half_rn(v.y);
            __half hz = __float2half_rn(v.z);
            __half hw = __float2half_rn(v.w);
            __half2 h01 = __halves2half2(hx, hy);
            __half2 h23 = __halves2half2(hz, hw);
            __half2 l01 = __halves2half2(
                __float2half_rn(v.x - __half2float(hx)),
                __float2half_rn(v.y - __half2float(hy)));
            __half2 l23 = __halves2half2(
                __float2half_rn(v.z - __half2float(hz)),
                __float2half_rn(v.w - __half2float(hw)));
            uint32_t hu0 = *(uint32_t*)&h01, hu1 = *(uint32_t*)&h23;
            uint32_t lu0 = *(uint32_t*)&l01, lu1 = *(uint32_t*)&l23;
            asm volatile("st.shared.v2.b32 [%0], {%1, %2};"
                         :: "r"(base + 0 * TILE_PB + off), "r"(hu0), "r"(hu1) : "memory");
            asm volatile("st.shared.v2.b32 [%0], {%1, %2};"
                         :: "r"(base + 1 * TILE_PB + off), "r"(lu0), "r"(lu1) : "memory");
        }
    };

    if (CONVERT_A) {
        ldg_A_f32(0);
        prefetch_B(0, 0);
        CP_ASYNC_COMMIT();
    } else {
        prefetch_A_f16(0, 0);
        prefetch_B(0, 0);
        CP_ASYNC_COMMIT();
    }

    for (int c = 0; c < NCH; ++c) {
        const int buf = c & 1;
        if (CONVERT_A) {
            sts_A_split(buf);
            if (c + 1 < NCH) {
                prefetch_B(c + 1, buf ^ 1);
                CP_ASYNC_COMMIT();
                CP_ASYNC_WAIT_1();
            } else {
                CP_ASYNC_WAIT_0();
            }
            __syncthreads();
            if (c + 1 < NCH) ldg_A_f32(c + 1);
        } else {
            if (c + 1 < NCH) {
                prefetch_A_f16(c + 1, buf ^ 1);
                prefetch_B(c + 1, buf ^ 1);
                CP_ASYNC_COMMIT();
                CP_ASYNC_WAIT_1();
            } else {
                CP_ASYNC_WAIT_0();
            }
            __syncthreads();
        }

        const uint32_t tb  = sb + buf * BUF_PB;
        const uint32_t ahB = tb + 0 * TILE_PB;
        const uint32_t alB = tb + 1 * TILE_PB;
        const uint32_t bhB = tb + 2 * TILE_PB;
        const uint32_t blB = tb + 3 * TILE_PB;

        #pragma unroll
        for (int ks = 0; ks < 2; ++ks) {
            const int kbyte = ks * 32;
            uint32_t ah[4][4], al[4][4], ph[4][2], pl[4][2];
            #pragma unroll
            for (int mi = 0; mi < 4; ++mi) {
                uint32_t off = (uint32_t)(aRow + mi * 16) * ROWB + kbyte + aSeg;
                LDSM_X4(ah[mi], ahB + off);
                LDSM_X4(al[mi], alB + off);
            }
            #pragma unroll
            for (int ni = 0; ni < 2; ++ni) {
                uint32_t off = (uint32_t)(bRow + ni * 16) * ROWB + kbyte + bSeg;
                uint32_t r[4];
                LDSM_X4(r, bhB + off);
                ph[2 * ni][0] = r[0]; ph[2 * ni][1] = r[1];
                ph[2 * ni + 1][0] = r[2]; ph[2 * ni + 1][1] = r[3];
                LDSM_X4(r, blB + off);
                pl[2 * ni][0] = r[0]; pl[2 * ni][1] = r[1];
                pl[2 * ni + 1][0] = r[2]; pl[2 * ni + 1][1] = r[3];
            }
            #pragma unroll
            for (int mi = 0; mi < 4; ++mi)
                #pragma unroll
                for (int nf = 0; nf < 4; ++nf) {
                    mma_f16(acc[mi][nf], ah[mi], ph[nf]);
                    mma_f16(acc[mi][nf], ah[mi], pl[nf]);
                    mma_f16(acc[mi][nf], al[mi], ph[nf]);
                }
        }
        __syncthreads();
    }

    #pragma unroll
    for (int mi = 0; mi < 4; ++mi) {
        int r0 = bm + wm + mi * 16 + (lane >> 2);
        #pragma unroll
        for (int nf = 0; nf < 4; ++nf) {
            int cn = bn + wn + nf * 8 + 2 * (lane & 3);
            float b0 = bias[cn], b1 = bias[cn + 1];
            #pragma unroll
            for (int half_ = 0; half_ < 2; ++half_) {
                int r = r0 + half_ * 8;
                float o0 = acc[mi][nf][2 * half_ + 0] + b0;
                float o1 = acc[mi][nf][2 * half_ + 1] + b1;
                if (RELU) { o0 = fmaxf(o0, 0.f); o1 = fmaxf(o1, 0.f); }
                __half h0 = __float2half_rn(o0);
                __half h1 = __float2half_rn(o1);
                __half2 hh = __halves2half2(h0, h1);
                __half2 ll = __halves2half2(
                    __float2half_rn(o0 - __half2float(h0)),
                    __float2half_rn(o1 - __half2float(h1)));
                *(__half2*)&Oh[(size_t)r * DHD + cn] = hh;
                *(__half2*)&Ol[(size_t)r * DHD + cn] = ll;
            }
        }
    }
}

// ---------------------------------------------------------------------------
// Correlation, v3: 64x128 tiles, 128 threads, 2 CTAs/SM, 3-stage pipeline.
//   grid (QN/64, CN/128, 9) = 288 CTAs; 4 warps, warp tile 32x64.
//   fp16 3-term split: Ah*Ph + Ah*Pl + Al*Ph, fp32 accum.
// ---------------------------------------------------------------------------
#define BKC3     32
#define NCH3     (KCORR / BKC3)      // 1024
#define ROW3     80
#define T_A3     (64 * ROW3)         // 5120
#define T_P3     (128 * ROW3)        // 10240
#define OFF_AH3  0
#define OFF_AL3  (T_A3)
#define OFF_PH3  (2 * T_A3)
#define OFF_PL3  (2 * T_A3 + T_P3)
#define BUF3     (2 * T_A3 + 2 * T_P3)   // 30720
#define CORR_SMEM (3 * BUF3)             // 92160

__device__ __forceinline__ void corr_prefetch3(
    uint32_t sb, int buf, int c, int bm, int bn, int lag,
    const __half* __restrict__ Ah, const __half* __restrict__ Al,
    const __half* __restrict__ Ph, const __half* __restrict__ Pl,
    int tid)
{
    const int k0 = c * BKC3;
    const int t  = c >> 3;                       // k0 / 256
    const int d0 = (c & 7) << 5;                 // k0 % 256
    const int ts = (t + lag + TNT) & (TNT - 1);
    const int kb = ts * DHD + d0;

    const uint32_t base = sb + buf * BUF3;
    #pragma unroll
    for (int i = 0; i < 12; ++i) {
        int u = tid + i * 128;                   // 0..1535
        uint32_t dst;
        const __half* src;
        if (u < 256) {                           // Ah: 64 rows x 4 segs
            int row = u >> 2, seg = u & 3;
            dst = base + OFF_AH3 + row * ROW3 + seg * 16;
            src = Ah + (size_t)(bm + row) * KCORR + k0 + seg * 8;
        } else if (u < 512) {                    // Al
            int w = u - 256;
            int row = w >> 2, seg = w & 3;
            dst = base + OFF_AL3 + row * ROW3 + seg * 16;
            src = Al + (size_t)(bm + row) * KCORR + k0 + seg * 8;
        } else if (u < 1024) {                   // Ph: 128 rows x 4 segs
            int w = u - 512;
            int row = w >> 2, seg = w & 3;
            dst = base + OFF_PH3 + row * ROW3 + seg * 16;
            src = Ph + (size_t)(bn + row) * KCORR + kb + seg * 8;
        } else {                                 // Pl
            int w = u - 1024;
            int row = w >> 2, seg = w & 3;
            dst = base + OFF_PL3 + row * ROW3 + seg * 16;
            src = Pl + (size_t)(bn + row) * KCORR + kb + seg * 8;
        }
        CP_ASYNC_CG_16(dst, src);
    }
    CP_ASYNC_COMMIT();
}

__global__ __launch_bounds__(128, 2)
void corr_hmma_kernel(const __half* __restrict__ Ah,
                      const __half* __restrict__ Al,
                      const __half* __restrict__ Ph,
                      const __half* __restrict__ Pl) {
    const uint32_t sb = smem_u32(dsm);
    const int tid  = threadIdx.x;
    const int wid  = tid >> 5;
    const int lane = tid & 31;
    const int bm = blockIdx.x * 64;              // q tile (64 rows)
    const int bn = blockIdx.y * 128;             // c tile (128 cols)
    const int lag = (int)blockIdx.z - MAXLAG;

    const int wm = (wid >> 1) * 32;              // 0, 32
    const int wn = (wid & 1) * 64;               // 0, 64

    float acc[2][8][4];
    #pragma unroll
    for (int mi = 0; mi < 2; ++mi)
        #pragma unroll
        for (int nf = 0; nf < 8; ++nf)
            #pragma unroll
            for (int r = 0; r < 4; ++r) acc[mi][nf][r] = 0.f;

    const int aRow = wm + (lane & 15);
    const int aSeg = (lane >> 4) << 4;
    const int bg   = lane >> 3;
    const int bRow = wn + ((bg >> 1) << 3) + (lane & 7);
    const int bSeg = (bg & 1) << 4;

    // double-buffered fragment registers (ks pipeline within chunk)
    uint32_t fah[2][2][4], fal[2][2][4], fbh[2][8][2], fbl[2][8][2];

    corr_prefetch3(sb, 0, 0, bm, bn, lag, Ah, Al, Ph, Pl, tid);
    corr_prefetch3(sb, 1, 1, bm, bn, lag, Ah, Al, Ph, Pl, tid);

    for (int c = 0; c < NCH3; ++c) {
        const int buf = c % 3;
        if (c + 2 < NCH3)
            corr_prefetch3(sb, (c + 2) % 3, c + 2, bm, bn, lag,
                           Ah, Al, Ph, Pl, tid);
        if (c + 2 < NCH3)      CP_ASYNC_WAIT_2();
        else if (c + 1 < NCH3) CP_ASYNC_WAIT_1();
        else                   CP_ASYNC_WAIT_0();
        __syncthreads();

        const uint32_t tb  = sb + buf * BUF3;
        const uint32_t ahB = tb + OFF_AH3;
        const uint32_t alB = tb + OFF_AL3;
        const uint32_t phB = tb + OFF_PH3;
        const uint32_t plB = tb + OFF_PL3;

        // load fragments for ks = 0
        #pragma unroll
        for (int mi = 0; mi < 2; ++mi) {
            uint32_t off = (uint32_t)(aRow + mi * 16) * ROW3 + aSeg;
            LDSM_X4(fah[0][mi], ahB + off);
            LDSM_X4(fal[0][mi], alB + off);
        }
        #pragma unroll
        for (int ni = 0; ni < 4; ++ni) {
            uint32_t off = (uint32_t)(bRow + ni * 16) * ROW3 + bSeg;
            uint32_t r[4];
            LDSM_X4(r, phB + off);
            fbh[0][2 * ni][0] = r[0]; fbh[0][2 * ni][1] = r[1];
            fbh[0][2 * ni + 1][0] = r[2]; fbh[0][2 * ni + 1][1] = r[3];
            LDSM_X4(r, plB + off);
            fbl[0][2 * ni][0] = r[0]; fbl[0][2 * ni][1] = r[1];
            fbl[0][2 * ni + 1][0] = r[2]; fbl[0][2 * ni + 1][1] = r[3];
        }

        #pragma unroll
        for (int ks = 0; ks < 2; ++ks) {
            const int cur = ks;
            if (ks == 0) {   // prefetch ks=1 fragments
                const int kbyte = 32;
                #pragma unroll
                for (int mi = 0; mi < 2; ++mi) {
                    uint32_t off = (uint32_t)(aRow + mi * 16) * ROW3 + kbyte + aSeg;
                    LDSM_X4(fah[1][mi], ahB + off);
                    LDSM_X4(fal[1][mi], alB + off);
                }
                #pragma unroll
                for (int ni = 0; ni < 4; ++ni) {
                    uint32_t off = (uint32_t)(bRow + ni * 16) * ROW3 + kbyte + bSeg;
                    uint32_t r[4];
                    LDSM_X4(r, phB + off);
                    fbh[1][2 * ni][0] = r[0]; fbh[1][2 * ni][1] = r[1];
                    fbh[1][2 * ni + 1][0] = r[2]; fbh[1][2 * ni + 1][1] = r[3];
                    LDSM_X4(r, plB + off);
                    fbl[1][2 * ni][0] = r[0]; fbl[1][2 * ni][1] = r[1];
                    fbl[1][2 * ni + 1][0] = r[2]; fbl[1][2 * ni + 1][1] = r[3];
                }
            }
            #pragma unroll
            for (int mi = 0; mi < 2; ++mi)
                #pragma unroll
                for (int nf = 0; nf < 8; ++nf) {
                    mma_f16(acc[mi][nf], fah[cur][mi], fbh[cur][nf]);  // hi*hi
                    mma_f16(acc[mi][nf], fah[cur][mi], fbl[cur][nf]);  // hi*lo
                    mma_f16(acc[mi][nf], fal[cur][mi], fbh[cur][nf]);  // lo*hi
                }
        }
        __syncthreads();   // all warps done reading buf before it is refilled
    }

    float* Sz = g_S + (size_t)blockIdx.z * QN * CN;
    #pragma unroll
    for (int mi = 0; mi < 2; ++mi) {
        int r0 = bm + wm + mi * 16 + (lane >> 2);
        #pragma unroll
        for (int nf = 0; nf < 8; ++nf) {
            int col = bn + wn + nf * 8 + 2 * (lane & 3);
            float2 v0 = {acc[mi][nf][0], acc[mi][nf][1]};
            float2 v1 = {acc[mi][nf][2], acc[mi][nf][3]};
            *(float2*)&Sz[(size_t)r0 * CN + col]       = v0;
            *(float2*)&Sz[(size_t)(r0 + 8) * CN + col] = v1;
        }
    }
}

// ---------------------------------------------------------------------------
// Final max over lags
// ---------------------------------------------------------------------------
__global__ void maxlag_kernel(float* __restrict__ out) {
    int idx = blockIdx.x * blockDim.x + threadIdx.x;
    float m = g_S[idx];
    #pragma unroll
    for (int j = 1; j < NLAG; ++j)
        m = fmaxf(m, g_S[(size_t)j * QN * CN + idx]);
    out[idx] = m;
}

// ---------------------------------------------------------------------------
// Launch
// ---------------------------------------------------------------------------
extern "C" void kernel_launch(void* const* d_in, const int* in_sizes, int n_in,
                              void* d_out, int out_size) {
    const float* audio = (const float*)d_in[0];
    const float* video = (const float*)d_in[1];
    const float* a_w1  = (const float*)d_in[2];
    const float* a_b1  = (const float*)d_in[3];
    const float* a_w2  = (const float*)d_in[4];
    const float* a_b2  = (const float*)d_in[5];
    const float* v_w1  = (const float*)d_in[6];
    const float* v_b1  = (const float*)d_in[7];
    const float* v_w2  = (const float*)d_in[8];
    const float* v_b2  = (const float*)d_in[9];
    const float* W     = (const float*)d_in[10];
    float* out = (float*)d_out;

    float *gWc, *gbc;
    __half *gHh, *gHl, *gAhf, *gAlf, *gPhf, *gPlf;
    __half *gW1ah, *gW1al, *gW1vh, *gW1vl, *gW2ah, *gW2al, *gWcth, *gWctl;
    cudaGetSymbolAddress((void**)&gHh,  g_Hh);
    cudaGetSymbolAddress((void**)&gHl,  g_Hl);
    cudaGetSymbolAddress((void**)&gAhf, g_Ahf);
    cudaGetSymbolAddress((void**)&gAlf, g_Alf);
    cudaGetSymbolAddress((void**)&gPhf, g_Phf);
    cudaGetSymbolAddress((void**)&gPlf, g_Plf);
    cudaGetSymbolAddress((void**)&gWc, g_Wc);
    cudaGetSymbolAddress((void**)&gbc, g_bc);
    cudaGetSymbolAddress((void**)&gW1ah, g_W1ah);
    cudaGetSymbolAddress((void**)&gW1al, g_W1al);
    cudaGetSymbolAddress((void**)&gW1vh, g_W1vh);
    cudaGetSymbolAddress((void**)&gW1vl, g_W1vl);
    cudaGetSymbolAddress((void**)&gW2ah, g_W2ah);
    cudaGetSymbolAddress((void**)&gW2al, g_W2al);
    cudaGetSymbolAddress((void**)&gWcth, g_Wcth);
    cudaGetSymbolAddress((void**)&gWctl, g_Wctl);

    cudaFuncSetAttribute(corr_hmma_kernel,
                         cudaFuncAttributeMaxDynamicSharedMemorySize, CORR_SMEM);
    cudaFuncSetAttribute(mlp_hmma_kernel<true, true>,
                         cudaFuncAttributeMaxDynamicSharedMemorySize, HMMA_SMEM);
    cudaFuncSetAttribute(mlp_hmma_kernel<false, false>,
                         cudaFuncAttributeMaxDynamicSharedMemorySize, HMMA_SMEM);

    // 0) prep: fold Wc, split+transpose all weights
    prep_w_kernel<<<DHD, DHD>>>(v_w2, v_b2, W);
    split_t_kernel<<<DHD, 256>>>(a_w1, gW1ah, gW1al, DIN);
    split_t_kernel<<<DHD, 256>>>(v_w1, gW1vh, gW1vl, DIN);
    split_t_kernel<<<DHD, 256>>>(a_w2, gW2ah, gW2al, DHD);
    split_t_kernel<<<DHD, 256>>>(gWc,  gWcth, gWctl, DHD);

    const dim3 mlp_grid(MROWS / 128, DHD / 128);   // 512 x 2

    // 1) audio MLP on HMMA
    mlp_hmma_kernel<true,  true ><<<mlp_grid, 256, HMMA_SMEM>>>(
        audio, nullptr, nullptr, gW1ah, gW1al, a_b1, gHh, gHl, DIN);
    mlp_hmma_kernel<false, false><<<mlp_grid, 256, HMMA_SMEM>>>(
        nullptr, gHh, gHl, gW2ah, gW2al, a_b2, gAhf, gAlf, DHD);

    // 2) video MLP + folded projection on HMMA
    mlp_hmma_kernel<true,  true ><<<mlp_grid, 256, HMMA_SMEM>>>(
        video, nullptr, nullptr, gW1vh, gW1vl, v_b1, gHh, gHl, DIN);
    mlp_hmma_kernel<false, false><<<mlp_grid, 256, HMMA_SMEM>>>(
        nullptr, gHh, gHl, gWcth, gWctl, gbc, gPhf, gPlf, DHD);

    // 3) per-lag correlation: 64x128 tiles, 288 CTAs, 2 CTAs/SM
    corr_hmma_kernel<<<dim3(QN / 64, CN / 128, NLAG), 128, CORR_SMEM>>>(
        gAhf, gAlf, gPhf, gPlf);

    // 4) max over lags
    maxlag_kernel<<<(QN * CN) / 256, 256>>>(out);
}

// round 8
// speedup vs baseline: 1.0890x; 1.0890x over previous
#include <cuda_runtime.h>
#include <cuda_fp16.h>
#include <cstdint>

// Problem dims (fixed by the reference)
#define QN   512
#define CN   512
#define TNT  128
#define DIN  512
#define DHD  256
#define KCORR (TNT * DHD)   // 32768
#define MAXLAG 4
#define NLAG  9             // lags -4..4
#define MROWS (QN * TNT)    // 65536

// ---------------------------------------------------------------------------
// Scratch (static device globals; no allocation allowed)
// ---------------------------------------------------------------------------
__device__ __half g_Hh [MROWS * DHD];   // hidden hi (reused audio/video)
__device__ __half g_Hl [MROWS * DHD];   // hidden lo
__device__ __half g_Ahf[MROWS * DHD];   // audio hi  [Q, T*DH]
__device__ __half g_Alf[MROWS * DHD];   // audio lo
__device__ __half g_Phf[MROWS * DHD];   // video hi  [C, T*DH]
__device__ __half g_Plf[MROWS * DHD];   // video lo
__device__ float g_Wc[DHD * DHD];       // folded v_w2 @ W (fp32)
__device__ float g_bc[DHD];             // folded v_b2 @ W
// pre-split, pre-transposed weights: [N][K], K contiguous (fp16 hi/lo)
__device__ __half g_W1ah[DHD * DIN], g_W1al[DHD * DIN];
__device__ __half g_W1vh[DHD * DIN], g_W1vl[DHD * DIN];
__device__ __half g_W2ah[DHD * DHD], g_W2al[DHD * DHD];
__device__ __half g_Wcth[DHD * DHD], g_Wctl[DHD * DHD];
__device__ float g_S [NLAG * QN * CN];  // per-lag scores

// ---------------------------------------------------------------------------
// Portable PTX helpers (valid on compute_103 virtual target)
// ---------------------------------------------------------------------------
__device__ __forceinline__ uint32_t smem_u32(const void* p) {
    uint32_t a;
    asm("{ .reg .u64 t; cvta.to.shared.u64 t, %1; cvt.u32.u64 %0, t; }"
        : "=r"(a) : "l"(p));
    return a;
}

#define CP_ASYNC_16(dst, src) \
    asm volatile("cp.async.ca.shared.global [%0], [%1], 16;" \
        :: "r"(dst), "l"(src) : "memory")
#define CP_ASYNC_CG_16(dst, src) \
    asm volatile("cp.async.cg.shared.global [%0], [%1], 16;" \
        :: "r"(dst), "l"(src) : "memory")
#define CP_ASYNC_COMMIT() asm volatile("cp.async.commit_group;" ::: "memory")
#define CP_ASYNC_WAIT_1() asm volatile("cp.async.wait_group 1;" ::: "memory")
#define CP_ASYNC_WAIT_0() asm volatile("cp.async.wait_group 0;" ::: "memory")

#define LDSM_X4(r, addr) \
    asm volatile("ldmatrix.sync.aligned.m8n8.x4.shared.b16 {%0,%1,%2,%3}, [%4];" \
        : "=r"((r)[0]), "=r"((r)[1]), "=r"((r)[2]), "=r"((r)[3]) : "r"(addr))

__device__ __forceinline__ void mma_f16(float* c, const uint32_t* a,
                                        const uint32_t* b) {
    asm volatile(
        "mma.sync.aligned.m16n8k16.row.col.f32.f16.f16.f32 "
        "{%0,%1,%2,%3}, {%4,%5,%6,%7}, {%8,%9}, {%0,%1,%2,%3};"
        : "+f"(c[0]), "+f"(c[1]), "+f"(c[2]), "+f"(c[3])
        : "r"(a[0]), "r"(a[1]), "r"(a[2]), "r"(a[3]), "r"(b[0]), "r"(b[1]));
}

// ---------------------------------------------------------------------------
// Prep: fold v_w2 @ W -> g_Wc, g_bc
// ---------------------------------------------------------------------------
__global__ void prep_w_kernel(const float* __restrict__ v_w2,
                              const float* __restrict__ v_b2,
                              const float* __restrict__ W) {
    int i = blockIdx.x;
    int j = threadIdx.x;
    float acc = 0.f;
    #pragma unroll 8
    for (int k = 0; k < DHD; ++k)
        acc += v_w2[i * DHD + k] * W[k * DHD + j];
    g_Wc[i * DHD + j] = acc;
    if (i == 0) {
        float accb = 0.f;
        #pragma unroll 8
        for (int k = 0; k < DHD; ++k)
            accb += v_b2[k] * W[k * DHD + j];
        g_bc[j] = accb;
    }
}

// Prep: transpose + split fp32 [K, 256] -> fp16 hi/lo [256][K]
__global__ void split_t_kernel(const float* __restrict__ in,
                               __half* __restrict__ oh,
                               __half* __restrict__ ol, int K) {
    int n = blockIdx.x;
    for (int k = threadIdx.x; k < K; k += blockDim.x) {
        float v = in[(size_t)k * DHD + n];
        __half h = __float2half_rn(v);
        __half l = __float2half_rn(v - __half2float(h));
        oh[(size_t)n * K + k] = h;
        ol[(size_t)n * K + k] = l;
    }
}

// ---------------------------------------------------------------------------
// MLP tiling constants
// ---------------------------------------------------------------------------
#define BKC     32                  // K elems per chunk (MLP)
#define ROWB    80                  // padded row stride bytes (64 data + 16)
#define TILE_PB (128 * ROWB)        // 10240
#define BUF_PB  (4 * TILE_PB)       // Ah, Al, Bh, Bl
#define HMMA_SMEM (2 * BUF_PB)      // 81920

extern __shared__ char dsm[];

// ---------------------------------------------------------------------------
// MLP GEMM on HMMA (fp16 3-term split). 256 threads, 128x128 tile.
// ---------------------------------------------------------------------------
template <bool CONVERT_A, bool RELU>
__global__ __launch_bounds__(256, 1)
void mlp_hmma_kernel(const float* __restrict__ Af,
                     const __half* __restrict__ Ahg,
                     const __half* __restrict__ Alg,
                     const __half* __restrict__ Bh,
                     const __half* __restrict__ Bl,
                     const float* __restrict__ bias,
                     __half* __restrict__ Oh,
                     __half* __restrict__ Ol,
                     int K) {
    const uint32_t sb = smem_u32(dsm);
    const int tid  = threadIdx.x;
    const int wid  = tid >> 5;
    const int lane = tid & 31;
    const int bm = blockIdx.x * 128;
    const int bn = blockIdx.y * 128;
    const int NCH = K / BKC;

    const int wm = (wid >> 2) * 64;
    const int wn = (wid & 3) * 32;

    float acc[4][4][4];
    #pragma unroll
    for (int mi = 0; mi < 4; ++mi)
        #pragma unroll
        for (int nf = 0; nf < 4; ++nf)
            #pragma unroll
            for (int r = 0; r < 4; ++r) acc[mi][nf][r] = 0.f;

    const int aRow = wm + (lane & 15);
    const int aSeg = (lane >> 4) << 4;
    const int bg   = lane >> 3;
    const int bRow = wn + ((bg >> 1) << 3) + (lane & 7);
    const int bSeg = (bg & 1) << 4;

    float4 areg[4];

    auto prefetch_B = [&](int c, int buf) {
        const int k0 = c * BKC;
        const uint32_t base = sb + buf * BUF_PB;
        #pragma unroll
        for (int i = 0; i < 4; ++i) {
            int u = tid + i * 256;
            int tile = 2 + (u >> 9);
            int w = u & 511;
            int row = w >> 2, seg = w & 3;
            uint32_t dst = base + tile * TILE_PB + row * ROWB + seg * 16;
            const __half* src =
                ((u >> 9) == 0 ? Bh : Bl) + (size_t)(bn + row) * K + k0 + seg * 8;
            CP_ASYNC_16(dst, src);
        }
    };
    auto prefetch_A_f16 = [&](int c, int buf) {
        const int k0 = c * BKC;
        const uint32_t base = sb + buf * BUF_PB;
        #pragma unroll
        for (int i = 0; i < 4; ++i) {
            int u = tid + i * 256;
            int tile = u >> 9;
            int w = u & 511;
            int row = w >> 2, seg = w & 3;
            uint32_t dst = base + tile * TILE_PB + row * ROWB + seg * 16;
            const __half* src =
                (tile == 0 ? Ahg : Alg) + (size_t)(bm + row) * K + k0 + seg * 8;
            CP_ASYNC_16(dst, src);
        }
    };
    auto ldg_A_f32 = [&](int c) {
        const int k0 = c * BKC;
        #pragma unroll
        for (int i = 0; i < 4; ++i) {
            int s = tid + i * 256;
            int row = s >> 3, seg = s & 7;
            areg[i] = *(const float4*)&Af[(size_t)(bm + row) * K + k0 + seg * 4];
        }
    };
    auto sts_A_split = [&](int buf) {
        const uint32_t base = sb + buf * BUF_PB;
        #pragma unroll
        for (int i = 0; i < 4; ++i) {
            int s = tid + i * 256;
            int row = s >> 3, seg = s & 7;
            uint32_t off = row * ROWB + seg * 8;
            float4 v = areg[i];
            __half hx = __float2half_rn(v.x);
            __half hy = __float2half_rn(v.y);
            __half hz = __float2half_rn(v.z);
            __half hw = __float2half_rn(v.w);
            __half2 h01 = __halves2half2(hx, hy);
            __half2 h23 = __halves2half2(hz, hw);
            __half2 l01 = __halves2half2(
                __float2half_rn(v.x - __half2float(hx)),
                __float2half_rn(v.y - __half2float(hy)));
            __half2 l23 = __halves2half2(
                __float2half_rn(v.z - __half2float(hz)),
                __float2half_rn(v.w - __half2float(hw)));
            uint32_t hu0 = *(uint32_t*)&h01, hu1 = *(uint32_t*)&h23;
            uint32_t lu0 = *(uint32_t*)&l01, lu1 = *(uint32_t*)&l23;
            asm volatile("st.shared.v2.b32 [%0], {%1, %2};"
                         :: "r"(base + 0 * TILE_PB + off), "r"(hu0), "r"(hu1) : "memory");
            asm volatile("st.shared.v2.b32 [%0], {%1, %2};"
                         :: "r"(base + 1 * TILE_PB + off), "r"(lu0), "r"(lu1) : "memory");
        }
    };

    if (CONVERT_A) {
        ldg_A_f32(0);
        prefetch_B(0, 0);
        CP_ASYNC_COMMIT();
    } else {
        prefetch_A_f16(0, 0);
        prefetch_B(0, 0);
        CP_ASYNC_COMMIT();
    }

    for (int c = 0; c < NCH; ++c) {
        const int buf = c & 1;
        if (CONVERT_A) {
            sts_A_split(buf);
            if (c + 1 < NCH) {
                prefetch_B(c + 1, buf ^ 1);
                CP_ASYNC_COMMIT();
                CP_ASYNC_WAIT_1();
            } else {
                CP_ASYNC_WAIT_0();
            }
            __syncthreads();
            if (c + 1 < NCH) ldg_A_f32(c + 1);
        } else {
            if (c + 1 < NCH) {
                prefetch_A_f16(c + 1, buf ^ 1);
                prefetch_B(c + 1, buf ^ 1);
                CP_ASYNC_COMMIT();
                CP_ASYNC_WAIT_1();
            } else {
                CP_ASYNC_WAIT_0();
            }
            __syncthreads();
        }

        const uint32_t tb  = sb + buf * BUF_PB;
        const uint32_t ahB = tb + 0 * TILE_PB;
        const uint32_t alB = tb + 1 * TILE_PB;
        const uint32_t bhB = tb + 2 * TILE_PB;
        const uint32_t blB = tb + 3 * TILE_PB;

        #pragma unroll
        for (int ks = 0; ks < 2; ++ks) {
            const int kbyte = ks * 32;
            uint32_t ah[4][4], al[4][4], ph[4][2], pl[4][2];
            #pragma unroll
            for (int mi = 0; mi < 4; ++mi) {
                uint32_t off = (uint32_t)(aRow + mi * 16) * ROWB + kbyte + aSeg;
                LDSM_X4(ah[mi], ahB + off);
                LDSM_X4(al[mi], alB + off);
            }
            #pragma unroll
            for (int ni = 0; ni < 2; ++ni) {
                uint32_t off = (uint32_t)(bRow + ni * 16) * ROWB + kbyte + bSeg;
                uint32_t r[4];
                LDSM_X4(r, bhB + off);
                ph[2 * ni][0] = r[0]; ph[2 * ni][1] = r[1];
                ph[2 * ni + 1][0] = r[2]; ph[2 * ni + 1][1] = r[3];
                LDSM_X4(r, blB + off);
                pl[2 * ni][0] = r[0]; pl[2 * ni][1] = r[1];
                pl[2 * ni + 1][0] = r[2]; pl[2 * ni + 1][1] = r[3];
            }
            #pragma unroll
            for (int mi = 0; mi < 4; ++mi)
                #pragma unroll
                for (int nf = 0; nf < 4; ++nf) {
                    mma_f16(acc[mi][nf], ah[mi], ph[nf]);
                    mma_f16(acc[mi][nf], ah[mi], pl[nf]);
                    mma_f16(acc[mi][nf], al[mi], ph[nf]);
                }
        }
        __syncthreads();
    }

    #pragma unroll
    for (int mi = 0; mi < 4; ++mi) {
        int r0 = bm + wm + mi * 16 + (lane >> 2);
        #pragma unroll
        for (int nf = 0; nf < 4; ++nf) {
            int cn = bn + wn + nf * 8 + 2 * (lane & 3);
            float b0 = bias[cn], b1 = bias[cn + 1];
            #pragma unroll
            for (int half_ = 0; half_ < 2; ++half_) {
                int r = r0 + half_ * 8;
                float o0 = acc[mi][nf][2 * half_ + 0] + b0;
                float o1 = acc[mi][nf][2 * half_ + 1] + b1;
                if (RELU) { o0 = fmaxf(o0, 0.f); o1 = fmaxf(o1, 0.f); }
                __half h0 = __float2half_rn(o0);
                __half h1 = __float2half_rn(o1);
                __half2 hh = __halves2half2(h0, h1);
                __half2 ll = __halves2half2(
                    __float2half_rn(o0 - __half2float(h0)),
                    __float2half_rn(o1 - __half2float(h1)));
                *(__half2*)&Oh[(size_t)r * DHD + cn] = hh;
                *(__half2*)&Ol[(size_t)r * DHD + cn] = ll;
            }
        }
    }
}

// ---------------------------------------------------------------------------
// Correlation, v4: 128x128 tile, 512 threads (16 warps, 4 per SMSP),
//   warp tile 32x32, BKC=64, 2-stage cp.async. grid 4x4x9 = 144 CTAs.
//   fp16 3-term split: Ah*Ph + Ah*Pl + Al*Ph, fp32 accum.
// ---------------------------------------------------------------------------
#define BKC4     64
#define NCH4     (KCORR / BKC4)      // 512
#define ROW4     144                 // 128B data + 16 pad
#define TILE4    (128 * ROW4)        // 18432
#define BUF4     (4 * TILE4)         // Ah, Al, Ph, Pl = 73728
#define CORR_SMEM (2 * BUF4)         // 147456

__device__ __forceinline__ void corr_prefetch4(
    uint32_t sb, int buf, int c, int bm, int bn, int lag,
    const __half* __restrict__ Ah, const __half* __restrict__ Al,
    const __half* __restrict__ Ph, const __half* __restrict__ Pl,
    int tid)
{
    const int k0 = c * BKC4;
    const int t  = c >> 2;                       // k0 / 256
    const int d0 = (c & 3) << 6;                 // k0 % 256
    const int ts = (t + lag + TNT) & (TNT - 1);
    const int kb = ts * DHD + d0;

    const uint32_t base = sb + buf * BUF4;
    #pragma unroll
    for (int i = 0; i < 8; ++i) {
        int u    = tid + i * 512;                // 0..4095
        int tile = u >> 10;                      // 0..3
        int w    = u & 1023;
        int row  = w >> 3;                       // 0..127
        int seg  = w & 7;                        // 16B segment
        uint32_t dst = base + tile * TILE4 + row * ROW4 + seg * 16;
        const __half* src;
        if (tile == 0)      src = Ah + (size_t)(bm + row) * KCORR + k0 + seg * 8;
        else if (tile == 1) src = Al + (size_t)(bm + row) * KCORR + k0 + seg * 8;
        else if (tile == 2) src = Ph + (size_t)(bn + row) * KCORR + kb + seg * 8;
        else                src = Pl + (size_t)(bn + row) * KCORR + kb + seg * 8;
        CP_ASYNC_CG_16(dst, src);
    }
    CP_ASYNC_COMMIT();
}

__global__ __launch_bounds__(512, 1)
void corr_hmma_kernel(const __half* __restrict__ Ah,
                      const __half* __restrict__ Al,
                      const __half* __restrict__ Ph,
                      const __half* __restrict__ Pl) {
    const uint32_t sb = smem_u32(dsm);
    const int tid  = threadIdx.x;
    const int wid  = tid >> 5;
    const int lane = tid & 31;
    const int bm = blockIdx.x * 128;
    const int bn = blockIdx.y * 128;
    const int lag = (int)blockIdx.z - MAXLAG;

    const int wm = (wid >> 2) * 32;              // 0,32,64,96
    const int wn = (wid & 3) * 32;               // 0,32,64,96

    float acc[2][4][4];
    #pragma unroll
    for (int mi = 0; mi < 2; ++mi)
        #pragma unroll
        for (int nf = 0; nf < 4; ++nf)
            #pragma unroll
            for (int r = 0; r < 4; ++r) acc[mi][nf][r] = 0.f;

    const int aRow = wm + (lane & 15);
    const int aSeg = (lane >> 4) << 4;
    const int bg   = lane >> 3;
    const int bRow = wn + ((bg >> 1) << 3) + (lane & 7);
    const int bSeg = (bg & 1) << 4;

    corr_prefetch4(sb, 0, 0, bm, bn, lag, Ah, Al, Ph, Pl, tid);

    for (int c = 0; c < NCH4; ++c) {
        const int buf = c & 1;
        if (c + 1 < NCH4) {
            corr_prefetch4(sb, buf ^ 1, c + 1, bm, bn, lag, Ah, Al, Ph, Pl, tid);
            CP_ASYNC_WAIT_1();
        } else {
            CP_ASYNC_WAIT_0();
        }
        __syncthreads();

        const uint32_t tb  = sb + buf * BUF4;
        const uint32_t ahB = tb + 0 * TILE4;
        const uint32_t alB = tb + 1 * TILE4;
        const uint32_t phB = tb + 2 * TILE4;
        const uint32_t plB = tb + 3 * TILE4;

        #pragma unroll
        for (int ks = 0; ks < 4; ++ks) {
            const int kbyte = ks * 32;
            uint32_t ah[2][4], al[2][4], ph[4][2], pl[4][2];
            #pragma unroll
            for (int mi = 0; mi < 2; ++mi) {
                uint32_t off = (uint32_t)(aRow + mi * 16) * ROW4 + kbyte + aSeg;
                LDSM_X4(ah[mi], ahB + off);
                LDSM_X4(al[mi], alB + off);
            }
            #pragma unroll
            for (int ni = 0; ni < 2; ++ni) {
                uint32_t off = (uint32_t)(bRow + ni * 16) * ROW4 + kbyte + bSeg;
                uint32_t r[4];
                LDSM_X4(r, phB + off);
                ph[2 * ni][0] = r[0]; ph[2 * ni][1] = r[1];
                ph[2 * ni + 1][0] = r[2]; ph[2 * ni + 1][1] = r[3];
                LDSM_X4(r, plB + off);
                pl[2 * ni][0] = r[0]; pl[2 * ni][1] = r[1];
                pl[2 * ni + 1][0] = r[2]; pl[2 * ni + 1][1] = r[3];
            }
            #pragma unroll
            for (int mi = 0; mi < 2; ++mi)
                #pragma unroll
                for (int nf = 0; nf < 4; ++nf) {
                    mma_f16(acc[mi][nf], ah[mi], ph[nf]);  // hi*hi
                    mma_f16(acc[mi][nf], ah[mi], pl[nf]);  // hi*lo
                    mma_f16(acc[mi][nf], al[mi], ph[nf]);  // lo*hi
                }
        }
        __syncthreads();
    }

    float* Sz = g_S + (size_t)blockIdx.z * QN * CN;
    #pragma unroll
    for (int mi = 0; mi < 2; ++mi) {
        int r0 = bm + wm + mi * 16 + (lane >> 2);
        #pragma unroll
        for (int nf = 0; nf < 4; ++nf) {
            int col = bn + wn + nf * 8 + 2 * (lane & 3);
            float2 v0 = {acc[mi][nf][0], acc[mi][nf][1]};
            float2 v1 = {acc[mi][nf][2], acc[mi][nf][3]};
            *(float2*)&Sz[(size_t)r0 * CN + col]       = v0;
            *(float2*)&Sz[(size_t)(r0 + 8) * CN + col] = v1;
        }
    }
}

// ---------------------------------------------------------------------------
// Final max over lags
// ---------------------------------------------------------------------------
__global__ void maxlag_kernel(float* __restrict__ out) {
    int idx = blockIdx.x * blockDim.x + threadIdx.x;
    float m = g_S[idx];
    #pragma unroll
    for (int j = 1; j < NLAG; ++j)
        m = fmaxf(m, g_S[(size_t)j * QN * CN + idx]);
    out[idx] = m;
}

// ---------------------------------------------------------------------------
// Launch
// ---------------------------------------------------------------------------
extern "C" void kernel_launch(void* const* d_in, const int* in_sizes, int n_in,
                              void* d_out, int out_size) {
    const float* audio = (const float*)d_in[0];
    const float* video = (const float*)d_in[1];
    const float* a_w1  = (const float*)d_in[2];
    const float* a_b1  = (const float*)d_in[3];
    const float* a_w2  = (const float*)d_in[4];
    const float* a_b2  = (const float*)d_in[5];
    const float* v_w1  = (const float*)d_in[6];
    const float* v_b1  = (const float*)d_in[7];
    const float* v_w2  = (const float*)d_in[8];
    const float* v_b2  = (const float*)d_in[9];
    const float* W     = (const float*)d_in[10];
    float* out = (float*)d_out;

    float *gWc, *gbc;
    __half *gHh, *gHl, *gAhf, *gAlf, *gPhf, *gPlf;
    __half *gW1ah, *gW1al, *gW1vh, *gW1vl, *gW2ah, *gW2al, *gWcth, *gWctl;
    cudaGetSymbolAddress((void**)&gHh,  g_Hh);
    cudaGetSymbolAddress((void**)&gHl,  g_Hl);
    cudaGetSymbolAddress((void**)&gAhf, g_Ahf);
    cudaGetSymbolAddress((void**)&gAlf, g_Alf);
    cudaGetSymbolAddress((void**)&gPhf, g_Phf);
    cudaGetSymbolAddress((void**)&gPlf, g_Plf);
    cudaGetSymbolAddress((void**)&gWc, g_Wc);
    cudaGetSymbolAddress((void**)&gbc, g_bc);
    cudaGetSymbolAddress((void**)&gW1ah, g_W1ah);
    cudaGetSymbolAddress((void**)&gW1al, g_W1al);
    cudaGetSymbolAddress((void**)&gW1vh, g_W1vh);
    cudaGetSymbolAddress((void**)&gW1vl, g_W1vl);
    cudaGetSymbolAddress((void**)&gW2ah, g_W2ah);
    cudaGetSymbolAddress((void**)&gW2al, g_W2al);
    cudaGetSymbolAddress((void**)&gWcth, g_Wcth);
    cudaGetSymbolAddress((void**)&gWctl, g_Wctl);

    cudaFuncSetAttribute(corr_hmma_kernel,
                         cudaFuncAttributeMaxDynamicSharedMemorySize, CORR_SMEM);
    cudaFuncSetAttribute(mlp_hmma_kernel<true, true>,
                         cudaFuncAttributeMaxDynamicSharedMemorySize, HMMA_SMEM);
    cudaFuncSetAttribute(mlp_hmma_kernel<false, false>,
                         cudaFuncAttributeMaxDynamicSharedMemorySize, HMMA_SMEM);

    // 0) prep: fold Wc, split+transpose all weights
    prep_w_kernel<<<DHD, DHD>>>(v_w2, v_b2, W);
    split_t_kernel<<<DHD, 256>>>(a_w1, gW1ah, gW1al, DIN);
    split_t_kernel<<<DHD, 256>>>(v_w1, gW1vh, gW1vl, DIN);
    split_t_kernel<<<DHD, 256>>>(a_w2, gW2ah, gW2al, DHD);
    split_t_kernel<<<DHD, 256>>>(gWc,  gWcth, gWctl, DHD);

    const dim3 mlp_grid(MROWS / 128, DHD / 128);   // 512 x 2

    // 1) audio MLP on HMMA
    mlp_hmma_kernel<true,  true ><<<mlp_grid, 256, HMMA_SMEM>>>(
        audio, nullptr, nullptr, gW1ah, gW1al, a_b1, gHh, gHl, DIN);
    mlp_hmma_kernel<false, false><<<mlp_grid, 256, HMMA_SMEM>>>(
        nullptr, gHh, gHl, gW2ah, gW2al, a_b2, gAhf, gAlf, DHD);

    // 2) video MLP + folded projection on HMMA
    mlp_hmma_kernel<true,  true ><<<mlp_grid, 256, HMMA_SMEM>>>(
        video, nullptr, nullptr, gW1vh, gW1vl, v_b1, gHh, gHl, DIN);
    mlp_hmma_kernel<false, false><<<mlp_grid, 256, HMMA_SMEM>>>(
        nullptr, gHh, gHl, gWcth, gWctl, gbc, gPhf, gPlf, DHD);

    // 3) per-lag correlation: 128x128 tiles, 512 threads, 144 CTAs
    corr_hmma_kernel<<<dim3(QN / 128, CN / 128, NLAG), 512, CORR_SMEM>>>(
        gAhf, gAlf, gPhf, gPlf);

    // 4) max over lags
    maxlag_kernel<<<(QN * CN) / 256, 256>>>(out);
}

// round 9
// speedup vs baseline: 2.0151x; 1.8503x over previous
#include <cuda_runtime.h>
#include <cuda_fp16.h>
#include <cstdint>

// Problem dims (fixed by the reference)
#define QN   512
#define CN   512
#define TNT  128
#define DIN  512
#define DHD  256
#define KCORR (TNT * DHD)   // 32768
#define MAXLAG 4
#define NLAG  9             // lags -4..4
#define MROWS (QN * TNT)    // 65536

// ---------------------------------------------------------------------------
// Scratch (static device globals; no allocation allowed)
// ---------------------------------------------------------------------------
__device__ __half g_Hh [MROWS * DHD];   // hidden hi (reused audio/video)
__device__ __half g_Hl [MROWS * DHD];   // hidden lo
__device__ __half g_Ahf[MROWS * DHD];   // audio features fp16  [Q, T*DH]
__device__ __half g_Phf[MROWS * DHD];   // projected video fp16 [C, T*DH]
__device__ float g_Wc[DHD * DHD];       // folded v_w2 @ W (fp32)
__device__ float g_bc[DHD];             // folded v_b2 @ W
// pre-split, pre-transposed weights: [N][K], K contiguous (fp16 hi/lo)
__device__ __half g_W1ah[DHD * DIN], g_W1al[DHD * DIN];
__device__ __half g_W1vh[DHD * DIN], g_W1vl[DHD * DIN];
__device__ __half g_W2ah[DHD * DHD], g_W2al[DHD * DHD];
__device__ __half g_Wcth[DHD * DHD], g_Wctl[DHD * DHD];
__device__ float g_S [NLAG * QN * CN];  // per-lag scores

// ---------------------------------------------------------------------------
// Portable PTX helpers (valid on compute_103 virtual target)
// ---------------------------------------------------------------------------
__device__ __forceinline__ uint32_t smem_u32(const void* p) {
    uint32_t a;
    asm("{ .reg .u64 t; cvta.to.shared.u64 t, %1; cvt.u32.u64 %0, t; }"
        : "=r"(a) : "l"(p));
    return a;
}

#define CP_ASYNC_16(dst, src) \
    asm volatile("cp.async.ca.shared.global [%0], [%1], 16;" \
        :: "r"(dst), "l"(src) : "memory")
#define CP_ASYNC_CG_16(dst, src) \
    asm volatile("cp.async.cg.shared.global [%0], [%1], 16;" \
        :: "r"(dst), "l"(src) : "memory")
#define CP_ASYNC_COMMIT() asm volatile("cp.async.commit_group;" ::: "memory")
#define CP_ASYNC_WAIT_1() asm volatile("cp.async.wait_group 1;" ::: "memory")
#define CP_ASYNC_WAIT_0() asm volatile("cp.async.wait_group 0;" ::: "memory")

#define LDSM_X4(r, addr) \
    asm volatile("ldmatrix.sync.aligned.m8n8.x4.shared.b16 {%0,%1,%2,%3}, [%4];" \
        : "=r"((r)[0]), "=r"((r)[1]), "=r"((r)[2]), "=r"((r)[3]) : "r"(addr))

__device__ __forceinline__ void mma_f16(float* c, const uint32_t* a,
                                        const uint32_t* b) {
    asm volatile(
        "mma.sync.aligned.m16n8k16.row.col.f32.f16.f16.f32 "
        "{%0,%1,%2,%3}, {%4,%5,%6,%7}, {%8,%9}, {%0,%1,%2,%3};"
        : "+f"(c[0]), "+f"(c[1]), "+f"(c[2]), "+f"(c[3])
        : "r"(a[0]), "r"(a[1]), "r"(a[2]), "r"(a[3]), "r"(b[0]), "r"(b[1]));
}

// ---------------------------------------------------------------------------
// Prep: fold v_w2 @ W -> g_Wc, g_bc
// ---------------------------------------------------------------------------
__global__ void prep_w_kernel(const float* __restrict__ v_w2,
                              const float* __restrict__ v_b2,
                              const float* __restrict__ W) {
    int i = blockIdx.x;
    int j = threadIdx.x;
    float acc = 0.f;
    #pragma unroll 8
    for (int k = 0; k < DHD; ++k)
        acc += v_w2[i * DHD + k] * W[k * DHD + j];
    g_Wc[i * DHD + j] = acc;
    if (i == 0) {
        float accb = 0.f;
        #pragma unroll 8
        for (int k = 0; k < DHD; ++k)
            accb += v_b2[k] * W[k * DHD + j];
        g_bc[j] = accb;
    }
}

// Prep: transpose + split fp32 [K, 256] -> fp16 hi/lo [256][K]
__global__ void split_t_kernel(const float* __restrict__ in,
                               __half* __restrict__ oh,
                               __half* __restrict__ ol, int K) {
    int n = blockIdx.x;
    for (int k = threadIdx.x; k < K; k += blockDim.x) {
        float v = in[(size_t)k * DHD + n];
        __half h = __float2half_rn(v);
        __half l = __float2half_rn(v - __half2float(h));
        oh[(size_t)n * K + k] = h;
        ol[(size_t)n * K + k] = l;
    }
}

// ---------------------------------------------------------------------------
// MLP tiling constants
// ---------------------------------------------------------------------------
#define BKC     32                  // K elems per chunk (MLP)
#define ROWB    80                  // padded row stride bytes (64 data + 16)
#define TILE_PB (128 * ROWB)        // 10240
#define BUF_PB  (4 * TILE_PB)       // Ah, Al, Bh, Bl
#define HMMA_SMEM (2 * BUF_PB)      // 81920

extern __shared__ char dsm[];

// ---------------------------------------------------------------------------
// MLP GEMM on HMMA (fp16 3-term split). 256 threads, 128x128 tile.
//   NEED_LO=false skips storing the lo output (used for the final features).
// ---------------------------------------------------------------------------
template <bool CONVERT_A, bool RELU, bool NEED_LO>
__global__ __launch_bounds__(256, 1)
void mlp_hmma_kernel(const float* __restrict__ Af,
                     const __half* __restrict__ Ahg,
                     const __half* __restrict__ Alg,
                     const __half* __restrict__ Bh,
                     const __half* __restrict__ Bl,
                     const float* __restrict__ bias,
                     __half* __restrict__ Oh,
                     __half* __restrict__ Ol,
                     int K) {
    const uint32_t sb = smem_u32(dsm);
    const int tid  = threadIdx.x;
    const int wid  = tid >> 5;
    const int lane = tid & 31;
    const int bm = blockIdx.x * 128;
    const int bn = blockIdx.y * 128;
    const int NCH = K / BKC;

    const int wm = (wid >> 2) * 64;
    const int wn = (wid & 3) * 32;

    float acc[4][4][4];
    #pragma unroll
    for (int mi = 0; mi < 4; ++mi)
        #pragma unroll
        for (int nf = 0; nf < 4; ++nf)
            #pragma unroll
            for (int r = 0; r < 4; ++r) acc[mi][nf][r] = 0.f;

    const int aRow = wm + (lane & 15);
    const int aSeg = (lane >> 4) << 4;
    const int bg   = lane >> 3;
    const int bRow = wn + ((bg >> 1) << 3) + (lane & 7);
    const int bSeg = (bg & 1) << 4;

    float4 areg[4];

    auto prefetch_B = [&](int c, int buf) {
        const int k0 = c * BKC;
        const uint32_t base = sb + buf * BUF_PB;
        #pragma unroll
        for (int i = 0; i < 4; ++i) {
            int u = tid + i * 256;
            int tile = 2 + (u >> 9);
            int w = u & 511;
            int row = w >> 2, seg = w & 3;
            uint32_t dst = base + tile * TILE_PB + row * ROWB + seg * 16;
            const __half* src =
                ((u >> 9) == 0 ? Bh : Bl) + (size_t)(bn + row) * K + k0 + seg * 8;
            CP_ASYNC_16(dst, src);
        }
    };
    auto prefetch_A_f16 = [&](int c, int buf) {
        const int k0 = c * BKC;
        const uint32_t base = sb + buf * BUF_PB;
        #pragma unroll
        for (int i = 0; i < 4; ++i) {
            int u = tid + i * 256;
            int tile = u >> 9;
            int w = u & 511;
            int row = w >> 2, seg = w & 3;
            uint32_t dst = base + tile * TILE_PB + row * ROWB + seg * 16;
            const __half* src =
                (tile == 0 ? Ahg : Alg) + (size_t)(bm + row) * K + k0 + seg * 8;
            CP_ASYNC_16(dst, src);
        }
    };
    auto ldg_A_f32 = [&](int c) {
        const int k0 = c * BKC;
        #pragma unroll
        for (int i = 0; i < 4; ++i) {
            int s = tid + i * 256;
            int row = s >> 3, seg = s & 7;
            areg[i] = *(const float4*)&Af[(size_t)(bm + row) * K + k0 + seg * 4];
        }
    };
    auto sts_A_split = [&](int buf) {
        const uint32_t base = sb + buf * BUF_PB;
        #pragma unroll
        for (int i = 0; i < 4; ++i) {
            int s = tid + i * 256;
            int row = s >> 3, seg = s & 7;
            uint32_t off = row * ROWB + seg * 8;
            float4 v = areg[i];
            __half hx = __float2half_rn(v.x);
            __half hy = __float2half_rn(v.y);
            __half hz = __float2half_rn(v.z);
            __half hw = __float2half_rn(v.w);
            __half2 h01 = __halves2half2(hx, hy);
            __half2 h23 = __halves2half2(hz, hw);
            __half2 l01 = __halves2half2(
                __float2half_rn(v.x - __half2float(hx)),
                __float2half_rn(v.y - __half2float(hy)));
            __half2 l23 = __halves2half2(
                __float2half_rn(v.z - __half2float(hz)),
                __float2half_rn(v.w - __half2float(hw)));
            uint32_t hu0 = *(uint32_t*)&h01, hu1 = *(uint32_t*)&h23;
            uint32_t lu0 = *(uint32_t*)&l01, lu1 = *(uint32_t*)&l23;
            asm volatile("st.shared.v2.b32 [%0], {%1, %2};"
                         :: "r"(base + 0 * TILE_PB + off), "r"(hu0), "r"(hu1) : "memory");
            asm volatile("st.shared.v2.b32 [%0], {%1, %2};"
                         :: "r"(base + 1 * TILE_PB + off), "r"(lu0), "r"(lu1) : "memory");
        }
    };

    if (CONVERT_A) {
        ldg_A_f32(0);
        prefetch_B(0, 0);
        CP_ASYNC_COMMIT();
    } else {
        prefetch_A_f16(0, 0);
        prefetch_B(0, 0);
        CP_ASYNC_COMMIT();
    }

    for (int c = 0; c < NCH; ++c) {
        const int buf = c & 1;
        if (CONVERT_A) {
            sts_A_split(buf);
            if (c + 1 < NCH) {
                prefetch_B(c + 1, buf ^ 1);
                CP_ASYNC_COMMIT();
                CP_ASYNC_WAIT_1();
            } else {
                CP_ASYNC_WAIT_0();
            }
            __syncthreads();
            if (c + 1 < NCH) ldg_A_f32(c + 1);
        } else {
            if (c + 1 < NCH) {
                prefetch_A_f16(c + 1, buf ^ 1);
                prefetch_B(c + 1, buf ^ 1);
                CP_ASYNC_COMMIT();
                CP_ASYNC_WAIT_1();
            } else {
                CP_ASYNC_WAIT_0();
            }
            __syncthreads();
        }

        const uint32_t tb  = sb + buf * BUF_PB;
        const uint32_t ahB = tb + 0 * TILE_PB;
        const uint32_t alB = tb + 1 * TILE_PB;
        const uint32_t bhB = tb + 2 * TILE_PB;
        const uint32_t blB = tb + 3 * TILE_PB;

        #pragma unroll
        for (int ks = 0; ks < 2; ++ks) {
            const int kbyte = ks * 32;
            uint32_t ah[4][4], al[4][4], ph[4][2], pl[4][2];
            #pragma unroll
            for (int mi = 0; mi < 4; ++mi) {
                uint32_t off = (uint32_t)(aRow + mi * 16) * ROWB + kbyte + aSeg;
                LDSM_X4(ah[mi], ahB + off);
                LDSM_X4(al[mi], alB + off);
            }
            #pragma unroll
            for (int ni = 0; ni < 2; ++ni) {
                uint32_t off = (uint32_t)(bRow + ni * 16) * ROWB + kbyte + bSeg;
                uint32_t r[4];
                LDSM_X4(r, bhB + off);
                ph[2 * ni][0] = r[0]; ph[2 * ni][1] = r[1];
                ph[2 * ni + 1][0] = r[2]; ph[2 * ni + 1][1] = r[3];
                LDSM_X4(r, blB + off);
                pl[2 * ni][0] = r[0]; pl[2 * ni][1] = r[1];
                pl[2 * ni + 1][0] = r[2]; pl[2 * ni + 1][1] = r[3];
            }
            #pragma unroll
            for (int mi = 0; mi < 4; ++mi)
                #pragma unroll
                for (int nf = 0; nf < 4; ++nf) {
                    mma_f16(acc[mi][nf], ah[mi], ph[nf]);
                    mma_f16(acc[mi][nf], ah[mi], pl[nf]);
                    mma_f16(acc[mi][nf], al[mi], ph[nf]);
                }
        }
        __syncthreads();
    }

    #pragma unroll
    for (int mi = 0; mi < 4; ++mi) {
        int r0 = bm + wm + mi * 16 + (lane >> 2);
        #pragma unroll
        for (int nf = 0; nf < 4; ++nf) {
            int cn = bn + wn + nf * 8 + 2 * (lane & 3);
            float b0 = bias[cn], b1 = bias[cn + 1];
            #pragma unroll
            for (int half_ = 0; half_ < 2; ++half_) {
                int r = r0 + half_ * 8;
                float o0 = acc[mi][nf][2 * half_ + 0] + b0;
                float o1 = acc[mi][nf][2 * half_ + 1] + b1;
                if (RELU) { o0 = fmaxf(o0, 0.f); o1 = fmaxf(o1, 0.f); }
                __half h0 = __float2half_rn(o0);
                __half h1 = __float2half_rn(o1);
                __half2 hh = __halves2half2(h0, h1);
                *(__half2*)&Oh[(size_t)r * DHD + cn] = hh;
                if (NEED_LO) {
                    __half2 ll = __halves2half2(
                        __float2half_rn(o0 - __half2float(h0)),
                        __float2half_rn(o1 - __half2float(h1)));
                    *(__half2*)&Ol[(size_t)r * DHD + cn] = ll;
                }
            }
        }
    }
}

// ---------------------------------------------------------------------------
// Correlation, v5: SINGLE fp16 term (hi*hi), R5-proven structure.
//   128x128 tile, 256 threads, 8 warps, warp tile 64x32, BKC=128 (8 k16
//   steps), register ks double-buffer, 2-stage cp.async. 144 CTAs, one wave.
// ---------------------------------------------------------------------------
#define BKC5     128
#define NCH5     (KCORR / BKC5)      // 256
#define ROW5     272                 // 256B data + 16 pad
#define TILE5    (128 * ROW5)        // 34816
#define BUF5     (2 * TILE5)         // Ah, Ph = 69632
#define CORR_SMEM (2 * BUF5)         // 139264

__device__ __forceinline__ void corr_prefetch5(
    uint32_t sb, int buf, int c, int bm, int bn, int lag,
    const __half* __restrict__ Ah, const __half* __restrict__ Ph, int tid)
{
    const int k0 = c * BKC5;
    const int t  = c >> 1;                       // k0 / 256
    const int d0 = (c & 1) << 7;                 // k0 % 256
    const int ts = (t + lag + TNT) & (TNT - 1);
    const int kb = ts * DHD + d0;

    const uint32_t base = sb + buf * BUF5;
    #pragma unroll
    for (int i = 0; i < 16; ++i) {
        int u    = tid + i * 256;                // 0..4095
        int tile = u >> 11;                      // 0..1
        int w    = u & 2047;
        int row  = w >> 4;                       // 0..127
        int seg  = w & 15;                       // 16B segment
        uint32_t dst = base + tile * TILE5 + row * ROW5 + seg * 16;
        const __half* src = (tile == 0)
            ? Ah + (size_t)(bm + row) * KCORR + k0 + seg * 8
            : Ph + (size_t)(bn + row) * KCORR + kb + seg * 8;
        CP_ASYNC_CG_16(dst, src);
    }
    CP_ASYNC_COMMIT();
}

__global__ __launch_bounds__(256, 1)
void corr_hmma_kernel(const __half* __restrict__ Ah,
                      const __half* __restrict__ Ph) {
    const uint32_t sb = smem_u32(dsm);
    const int tid  = threadIdx.x;
    const int wid  = tid >> 5;
    const int lane = tid & 31;
    const int bm = blockIdx.x * 128;
    const int bn = blockIdx.y * 128;
    const int lag = (int)blockIdx.z - MAXLAG;

    const int wm = (wid >> 2) * 64;              // 0, 64
    const int wn = (wid & 3) * 32;               // 0,32,64,96

    float acc[4][4][4];
    #pragma unroll
    for (int mi = 0; mi < 4; ++mi)
        #pragma unroll
        for (int nf = 0; nf < 4; ++nf)
            #pragma unroll
            for (int r = 0; r < 4; ++r) acc[mi][nf][r] = 0.f;

    const int aRow = wm + (lane & 15);
    const int aSeg = (lane >> 4) << 4;
    const int bg   = lane >> 3;
    const int bRow = wn + ((bg >> 1) << 3) + (lane & 7);
    const int bSeg = (bg & 1) << 4;

    // register ks double-buffer
    uint32_t fah[2][4][4], fbh[2][4][2];

    corr_prefetch5(sb, 0, 0, bm, bn, lag, Ah, Ph, tid);

    for (int c = 0; c < NCH5; ++c) {
        const int buf = c & 1;
        if (c + 1 < NCH5) {
            corr_prefetch5(sb, buf ^ 1, c + 1, bm, bn, lag, Ah, Ph, tid);
            CP_ASYNC_WAIT_1();
        } else {
            CP_ASYNC_WAIT_0();
        }
        __syncthreads();

        const uint32_t tb  = sb + buf * BUF5;
        const uint32_t ahB = tb + 0 * TILE5;
        const uint32_t phB = tb + 1 * TILE5;

        // load fragments for ks = 0
        #pragma unroll
        for (int mi = 0; mi < 4; ++mi) {
            uint32_t off = (uint32_t)(aRow + mi * 16) * ROW5 + aSeg;
            LDSM_X4(fah[0][mi], ahB + off);
        }
        #pragma unroll
        for (int ni = 0; ni < 2; ++ni) {
            uint32_t off = (uint32_t)(bRow + ni * 16) * ROW5 + bSeg;
            uint32_t r[4];
            LDSM_X4(r, phB + off);
            fbh[0][2 * ni][0] = r[0]; fbh[0][2 * ni][1] = r[1];
            fbh[0][2 * ni + 1][0] = r[2]; fbh[0][2 * ni + 1][1] = r[3];
        }

        #pragma unroll
        for (int ks = 0; ks < 8; ++ks) {
            const int cur = ks & 1;
            if (ks < 7) {
                const int nxt = cur ^ 1;
                const int kbyte = (ks + 1) * 32;
                #pragma unroll
                for (int mi = 0; mi < 4; ++mi) {
                    uint32_t off = (uint32_t)(aRow + mi * 16) * ROW5 + kbyte + aSeg;
                    LDSM_X4(fah[nxt][mi], ahB + off);
                }
                #pragma unroll
                for (int ni = 0; ni < 2; ++ni) {
                    uint32_t off = (uint32_t)(bRow + ni * 16) * ROW5 + kbyte + bSeg;
                    uint32_t r[4];
                    LDSM_X4(r, phB + off);
                    fbh[nxt][2 * ni][0] = r[0]; fbh[nxt][2 * ni][1] = r[1];
                    fbh[nxt][2 * ni + 1][0] = r[2]; fbh[nxt][2 * ni + 1][1] = r[3];
                }
            }
            #pragma unroll
            for (int mi = 0; mi < 4; ++mi)
                #pragma unroll
                for (int nf = 0; nf < 4; ++nf)
                    mma_f16(acc[mi][nf], fah[cur][mi], fbh[cur][nf]);
        }
        __syncthreads();
    }

    float* Sz = g_S + (size_t)blockIdx.z * QN * CN;
    #pragma unroll
    for (int mi = 0; mi < 4; ++mi) {
        int r0 = bm + wm + mi * 16 + (lane >> 2);
        #pragma unroll
        for (int nf = 0; nf < 4; ++nf) {
            int col = bn + wn + nf * 8 + 2 * (lane & 3);
            float2 v0 = {acc[mi][nf][0], acc[mi][nf][1]};
            float2 v1 = {acc[mi][nf][2], acc[mi][nf][3]};
            *(float2*)&Sz[(size_t)r0 * CN + col]       = v0;
            *(float2*)&Sz[(size_t)(r0 + 8) * CN + col] = v1;
        }
    }
}

// ---------------------------------------------------------------------------
// Final max over lags
// ---------------------------------------------------------------------------
__global__ void maxlag_kernel(float* __restrict__ out) {
    int idx = blockIdx.x * blockDim.x + threadIdx.x;
    float m = g_S[idx];
    #pragma unroll
    for (int j = 1; j < NLAG; ++j)
        m = fmaxf(m, g_S[(size_t)j * QN * CN + idx]);
    out[idx] = m;
}

// ---------------------------------------------------------------------------
// Launch
// ---------------------------------------------------------------------------
extern "C" void kernel_launch(void* const* d_in, const int* in_sizes, int n_in,
                              void* d_out, int out_size) {
    const float* audio = (const float*)d_in[0];
    const float* video = (const float*)d_in[1];
    const float* a_w1  = (const float*)d_in[2];
    const float* a_b1  = (const float*)d_in[3];
    const float* a_w2  = (const float*)d_in[4];
    const float* a_b2  = (const float*)d_in[5];
    const float* v_w1  = (const float*)d_in[6];
    const float* v_b1  = (const float*)d_in[7];
    const float* v_w2  = (const float*)d_in[8];
    const float* v_b2  = (const float*)d_in[9];
    const float* W     = (const float*)d_in[10];
    float* out = (float*)d_out;

    float *gWc, *gbc;
    __half *gHh, *gHl, *gAhf, *gPhf;
    __half *gW1ah, *gW1al, *gW1vh, *gW1vl, *gW2ah, *gW2al, *gWcth, *gWctl;
    cudaGetSymbolAddress((void**)&gHh,  g_Hh);
    cudaGetSymbolAddress((void**)&gHl,  g_Hl);
    cudaGetSymbolAddress((void**)&gAhf, g_Ahf);
    cudaGetSymbolAddress((void**)&gPhf, g_Phf);
    cudaGetSymbolAddress((void**)&gWc, g_Wc);
    cudaGetSymbolAddress((void**)&gbc, g_bc);
    cudaGetSymbolAddress((void**)&gW1ah, g_W1ah);
    cudaGetSymbolAddress((void**)&gW1al, g_W1al);
    cudaGetSymbolAddress((void**)&gW1vh, g_W1vh);
    cudaGetSymbolAddress((void**)&gW1vl, g_W1vl);
    cudaGetSymbolAddress((void**)&gW2ah, g_W2ah);
    cudaGetSymbolAddress((void**)&gW2al, g_W2al);
    cudaGetSymbolAddress((void**)&gWcth, g_Wcth);
    cudaGetSymbolAddress((void**)&gWctl, g_Wctl);

    cudaFuncSetAttribute(corr_hmma_kernel,
                         cudaFuncAttributeMaxDynamicSharedMemorySize, CORR_SMEM);
    cudaFuncSetAttribute(mlp_hmma_kernel<true, true, true>,
                         cudaFuncAttributeMaxDynamicSharedMemorySize, HMMA_SMEM);
    cudaFuncSetAttribute(mlp_hmma_kernel<false, false, false>,
                         cudaFuncAttributeMaxDynamicSharedMemorySize, HMMA_SMEM);

    // 0) prep: fold Wc, split+transpose all weights
    prep_w_kernel<<<DHD, DHD>>>(v_w2, v_b2, W);
    split_t_kernel<<<DHD, 256>>>(a_w1, gW1ah, gW1al, DIN);
    split_t_kernel<<<DHD, 256>>>(v_w1, gW1vh, gW1vl, DIN);
    split_t_kernel<<<DHD, 256>>>(a_w2, gW2ah, gW2al, DHD);
    split_t_kernel<<<DHD, 256>>>(gWc,  gWcth, gWctl, DHD);

    const dim3 mlp_grid(MROWS / 128, DHD / 128);   // 512 x 2

    // 1) audio MLP on HMMA (layer2 emits fp16 features, hi only)
    mlp_hmma_kernel<true,  true,  true ><<<mlp_grid, 256, HMMA_SMEM>>>(
        audio, nullptr, nullptr, gW1ah, gW1al, a_b1, gHh, gHl, DIN);
    mlp_hmma_kernel<false, false, false><<<mlp_grid, 256, HMMA_SMEM>>>(
        nullptr, gHh, gHl, gW2ah, gW2al, a_b2, gAhf, nullptr, DHD);

    // 2) video MLP + folded projection on HMMA
    mlp_hmma_kernel<true,  true,  true ><<<mlp_grid, 256, HMMA_SMEM>>>(
        video, nullptr, nullptr, gW1vh, gW1vl, v_b1, gHh, gHl, DIN);
    mlp_hmma_kernel<false, false, false><<<mlp_grid, 256, HMMA_SMEM>>>(
        nullptr, gHh, gHl, gWcth, gWctl, gbc, gPhf, nullptr, DHD);

    // 3) per-lag correlation: single fp16 term, 144 CTAs, one wave
    corr_hmma_kernel<<<dim3(QN / 128, CN / 128, NLAG), 256, CORR_SMEM>>>(
        gAhf, gPhf);

    // 4) max over lags
    maxlag_kernel<<<(QN * CN) / 256, 256>>>(out);
}

// round 10
// speedup vs baseline: 2.2328x; 1.1080x over previous
#include <cuda_runtime.h>
#include <cuda_fp16.h>
#include <cstdint>

// Problem dims (fixed by the reference)
#define QN   512
#define CN   512
#define TNT  128
#define DIN  512
#define DHD  256
#define KCORR (TNT * DHD)   // 32768
#define MAXLAG 4
#define NLAG  9             // lags -4..4
#define MROWS (QN * TNT)    // 65536

// ---------------------------------------------------------------------------
// Scratch (static device globals; no allocation allowed)
// ---------------------------------------------------------------------------
__device__ __half g_Hh [MROWS * DHD];   // hidden hi (reused audio/video)
__device__ __half g_Hl [MROWS * DHD];   // hidden lo
__device__ __half g_Ahf[MROWS * DHD];   // audio features fp16  [Q, T*DH]
__device__ __half g_Phf[MROWS * DHD];   // projected video fp16 [C, T*DH]
__device__ float g_Wc[DHD * DHD];       // folded v_w2 @ W (fp32)
__device__ float g_bc[DHD];             // folded v_b2 @ W
// pre-converted, pre-transposed weights: [N][K], K contiguous (fp16 hi only)
__device__ __half g_W1ah[DHD * DIN];
__device__ __half g_W1vh[DHD * DIN];
__device__ __half g_W2ah[DHD * DHD];
__device__ __half g_Wcth[DHD * DHD];
__device__ float g_S [NLAG * QN * CN];  // per-lag scores

// ---------------------------------------------------------------------------
// Portable PTX helpers (valid on compute_103 virtual target)
// ---------------------------------------------------------------------------
__device__ __forceinline__ uint32_t smem_u32(const void* p) {
    uint32_t a;
    asm("{ .reg .u64 t; cvta.to.shared.u64 t, %1; cvt.u32.u64 %0, t; }"
        : "=r"(a) : "l"(p));
    return a;
}

#define CP_ASYNC_16(dst, src) \
    asm volatile("cp.async.ca.shared.global [%0], [%1], 16;" \
        :: "r"(dst), "l"(src) : "memory")
#define CP_ASYNC_CG_16(dst, src) \
    asm volatile("cp.async.cg.shared.global [%0], [%1], 16;" \
        :: "r"(dst), "l"(src) : "memory")
#define CP_ASYNC_COMMIT() asm volatile("cp.async.commit_group;" ::: "memory")
#define CP_ASYNC_WAIT_1() asm volatile("cp.async.wait_group 1;" ::: "memory")
#define CP_ASYNC_WAIT_0() asm volatile("cp.async.wait_group 0;" ::: "memory")

#define LDSM_X4(r, addr) \
    asm volatile("ldmatrix.sync.aligned.m8n8.x4.shared.b16 {%0,%1,%2,%3}, [%4];" \
        : "=r"((r)[0]), "=r"((r)[1]), "=r"((r)[2]), "=r"((r)[3]) : "r"(addr))

__device__ __forceinline__ void mma_f16(float* c, const uint32_t* a,
                                        const uint32_t* b) {
    asm volatile(
        "mma.sync.aligned.m16n8k16.row.col.f32.f16.f16.f32 "
        "{%0,%1,%2,%3}, {%4,%5,%6,%7}, {%8,%9}, {%0,%1,%2,%3};"
        : "+f"(c[0]), "+f"(c[1]), "+f"(c[2]), "+f"(c[3])
        : "r"(a[0]), "r"(a[1]), "r"(a[2]), "r"(a[3]), "r"(b[0]), "r"(b[1]));
}

// ---------------------------------------------------------------------------
// Prep: fold v_w2 @ W -> g_Wc, g_bc
// ---------------------------------------------------------------------------
__global__ void prep_w_kernel(const float* __restrict__ v_w2,
                              const float* __restrict__ v_b2,
                              const float* __restrict__ W) {
    int i = blockIdx.x;
    int j = threadIdx.x;
    float acc = 0.f;
    #pragma unroll 8
    for (int k = 0; k < DHD; ++k)
        acc += v_w2[i * DHD + k] * W[k * DHD + j];
    g_Wc[i * DHD + j] = acc;
    if (i == 0) {
        float accb = 0.f;
        #pragma unroll 8
        for (int k = 0; k < DHD; ++k)
            accb += v_b2[k] * W[k * DHD + j];
        g_bc[j] = accb;
    }
}

// Prep: transpose + convert fp32 [K, 256] -> fp16 [256][K] (hi only)
__global__ void convt_kernel(const float* __restrict__ in,
                             __half* __restrict__ oh, int K) {
    int n = blockIdx.x;
    for (int k = threadIdx.x; k < K; k += blockDim.x)
        oh[(size_t)n * K + k] = __float2half_rn(in[(size_t)k * DHD + n]);
}

// ---------------------------------------------------------------------------
// MLP tiling constants (3 tiles: Ah, Al, Bh)
// ---------------------------------------------------------------------------
#define BKC     32                  // K elems per chunk (MLP)
#define ROWB    80                  // padded row stride bytes (64 data + 16)
#define TILE_PB (128 * ROWB)        // 10240
#define BUF_PB  (3 * TILE_PB)       // Ah, Al, Bh = 30720
#define HMMA_SMEM (2 * BUF_PB)      // 61440

extern __shared__ char dsm[];

// ---------------------------------------------------------------------------
// MLP GEMM on HMMA, 2-term split: O = (relu?)( (Ah+Al) @ Bh' + bias )
//   layer1 (CONVERT_A=1): fp32 in, split to hi/lo in registers
//   layer2 (CONVERT_A=0): fp16 hi/lo in from gmem
//   NEED_LO selects whether lo output is stored (hidden yes, features no).
// ---------------------------------------------------------------------------
template <bool CONVERT_A, bool RELU, bool NEED_LO>
__global__ __launch_bounds__(256, 1)
void mlp_hmma_kernel(const float* __restrict__ Af,
                     const __half* __restrict__ Ahg,
                     const __half* __restrict__ Alg,
                     const __half* __restrict__ Bh,
                     const float* __restrict__ bias,
                     __half* __restrict__ Oh,
                     __half* __restrict__ Ol,
                     int K) {
    const uint32_t sb = smem_u32(dsm);
    const int tid  = threadIdx.x;
    const int wid  = tid >> 5;
    const int lane = tid & 31;
    const int bm = blockIdx.x * 128;
    const int bn = blockIdx.y * 128;
    const int NCH = K / BKC;

    const int wm = (wid >> 2) * 64;
    const int wn = (wid & 3) * 32;

    float acc[4][4][4];
    #pragma unroll
    for (int mi = 0; mi < 4; ++mi)
        #pragma unroll
        for (int nf = 0; nf < 4; ++nf)
            #pragma unroll
            for (int r = 0; r < 4; ++r) acc[mi][nf][r] = 0.f;

    const int aRow = wm + (lane & 15);
    const int aSeg = (lane >> 4) << 4;
    const int bg   = lane >> 3;
    const int bRow = wn + ((bg >> 1) << 3) + (lane & 7);
    const int bSeg = (bg & 1) << 4;

    float4 areg[4];

    auto prefetch_B = [&](int c, int buf) {
        const int k0 = c * BKC;
        const uint32_t base = sb + buf * BUF_PB;
        #pragma unroll
        for (int i = 0; i < 2; ++i) {
            int u = tid + i * 256;               // 0..511
            int row = u >> 2, seg = u & 3;
            uint32_t dst = base + 2 * TILE_PB + row * ROWB + seg * 16;
            const __half* src = Bh + (size_t)(bn + row) * K + k0 + seg * 8;
            CP_ASYNC_16(dst, src);
        }
    };
    auto prefetch_A_f16 = [&](int c, int buf) {
        const int k0 = c * BKC;
        const uint32_t base = sb + buf * BUF_PB;
        #pragma unroll
        for (int i = 0; i < 4; ++i) {
            int u = tid + i * 256;               // 0..1023
            int tile = u >> 9;                   // 0..1
            int w = u & 511;
            int row = w >> 2, seg = w & 3;
            uint32_t dst = base + tile * TILE_PB + row * ROWB + seg * 16;
            const __half* src =
                (tile == 0 ? Ahg : Alg) + (size_t)(bm + row) * K + k0 + seg * 8;
            CP_ASYNC_16(dst, src);
        }
    };
    auto ldg_A_f32 = [&](int c) {
        const int k0 = c * BKC;
        #pragma unroll
        for (int i = 0; i < 4; ++i) {
            int s = tid + i * 256;
            int row = s >> 3, seg = s & 7;
            areg[i] = *(const float4*)&Af[(size_t)(bm + row) * K + k0 + seg * 4];
        }
    };
    auto sts_A_split = [&](int buf) {
        const uint32_t base = sb + buf * BUF_PB;
        #pragma unroll
        for (int i = 0; i < 4; ++i) {
            int s = tid + i * 256;
            int row = s >> 3, seg = s & 7;
            uint32_t off = row * ROWB + seg * 8;
            float4 v = areg[i];
            __half hx = __float2half_rn(v.x);
            __half hy = __float2half_rn(v.y);
            __half hz = __float2half_rn(v.z);
            __half hw = __float2half_rn(v.w);
            __half2 h01 = __halves2half2(hx, hy);
            __half2 h23 = __halves2half2(hz, hw);
            __half2 l01 = __halves2half2(
                __float2half_rn(v.x - __half2float(hx)),
                __float2half_rn(v.y - __half2float(hy)));
            __half2 l23 = __halves2half2(
                __float2half_rn(v.z - __half2float(hz)),
                __float2half_rn(v.w - __half2float(hw)));
            uint32_t hu0 = *(uint32_t*)&h01, hu1 = *(uint32_t*)&h23;
            uint32_t lu0 = *(uint32_t*)&l01, lu1 = *(uint32_t*)&l23;
            asm volatile("st.shared.v2.b32 [%0], {%1, %2};"
                         :: "r"(base + 0 * TILE_PB + off), "r"(hu0), "r"(hu1) : "memory");
            asm volatile("st.shared.v2.b32 [%0], {%1, %2};"
                         :: "r"(base + 1 * TILE_PB + off), "r"(lu0), "r"(lu1) : "memory");
        }
    };

    if (CONVERT_A) {
        ldg_A_f32(0);
        prefetch_B(0, 0);
        CP_ASYNC_COMMIT();
    } else {
        prefetch_A_f16(0, 0);
        prefetch_B(0, 0);
        CP_ASYNC_COMMIT();
    }

    for (int c = 0; c < NCH; ++c) {
        const int buf = c & 1;
        if (CONVERT_A) {
            sts_A_split(buf);
            if (c + 1 < NCH) {
                prefetch_B(c + 1, buf ^ 1);
                CP_ASYNC_COMMIT();
                CP_ASYNC_WAIT_1();
            } else {
                CP_ASYNC_WAIT_0();
            }
            __syncthreads();
            if (c + 1 < NCH) ldg_A_f32(c + 1);
        } else {
            if (c + 1 < NCH) {
                prefetch_A_f16(c + 1, buf ^ 1);
                prefetch_B(c + 1, buf ^ 1);
                CP_ASYNC_COMMIT();
                CP_ASYNC_WAIT_1();
            } else {
                CP_ASYNC_WAIT_0();
            }
            __syncthreads();
        }

        const uint32_t tb  = sb + buf * BUF_PB;
        const uint32_t ahB = tb + 0 * TILE_PB;
        const uint32_t alB = tb + 1 * TILE_PB;
        const uint32_t bhB = tb + 2 * TILE_PB;

        #pragma unroll
        for (int ks = 0; ks < 2; ++ks) {
            const int kbyte = ks * 32;
            uint32_t ah[4][4], al[4][4], ph[4][2];
            #pragma unroll
            for (int mi = 0; mi < 4; ++mi) {
                uint32_t off = (uint32_t)(aRow + mi * 16) * ROWB + kbyte + aSeg;
                LDSM_X4(ah[mi], ahB + off);
                LDSM_X4(al[mi], alB + off);
            }
            #pragma unroll
            for (int ni = 0; ni < 2; ++ni) {
                uint32_t off = (uint32_t)(bRow + ni * 16) * ROWB + kbyte + bSeg;
                uint32_t r[4];
                LDSM_X4(r, bhB + off);
                ph[2 * ni][0] = r[0]; ph[2 * ni][1] = r[1];
                ph[2 * ni + 1][0] = r[2]; ph[2 * ni + 1][1] = r[3];
            }
            #pragma unroll
            for (int mi = 0; mi < 4; ++mi)
                #pragma unroll
                for (int nf = 0; nf < 4; ++nf) {
                    mma_f16(acc[mi][nf], ah[mi], ph[nf]);   // hi * wh
                    mma_f16(acc[mi][nf], al[mi], ph[nf]);   // lo * wh
                }
        }
        __syncthreads();
    }

    #pragma unroll
    for (int mi = 0; mi < 4; ++mi) {
        int r0 = bm + wm + mi * 16 + (lane >> 2);
        #pragma unroll
        for (int nf = 0; nf < 4; ++nf) {
            int cn = bn + wn + nf * 8 + 2 * (lane & 3);
            float b0 = bias[cn], b1 = bias[cn + 1];
            #pragma unroll
            for (int half_ = 0; half_ < 2; ++half_) {
                int r = r0 + half_ * 8;
                float o0 = acc[mi][nf][2 * half_ + 0] + b0;
                float o1 = acc[mi][nf][2 * half_ + 1] + b1;
                if (RELU) { o0 = fmaxf(o0, 0.f); o1 = fmaxf(o1, 0.f); }
                __half h0 = __float2half_rn(o0);
                __half h1 = __float2half_rn(o1);
                __half2 hh = __halves2half2(h0, h1);
                *(__half2*)&Oh[(size_t)r * DHD + cn] = hh;
                if (NEED_LO) {
                    __half2 ll = __halves2half2(
                        __float2half_rn(o0 - __half2float(h0)),
                        __float2half_rn(o1 - __half2float(h1)));
                    *(__half2*)&Ol[(size_t)r * DHD + cn] = ll;
                }
            }
        }
    }
}

// ---------------------------------------------------------------------------
// Correlation, v5 (R9-proven): SINGLE fp16 term (hi*hi).
//   128x128 tile, 256 threads, 8 warps, warp tile 64x32, BKC=128 (8 k16
//   steps), register ks double-buffer, 2-stage cp.async. 144 CTAs, one wave.
// ---------------------------------------------------------------------------
#define BKC5     128
#define NCH5     (KCORR / BKC5)      // 256
#define ROW5     272                 // 256B data + 16 pad
#define TILE5    (128 * ROW5)        // 34816
#define BUF5     (2 * TILE5)         // Ah, Ph = 69632
#define CORR_SMEM (2 * BUF5)         // 139264

__device__ __forceinline__ void corr_prefetch5(
    uint32_t sb, int buf, int c, int bm, int bn, int lag,
    const __half* __restrict__ Ah, const __half* __restrict__ Ph, int tid)
{
    const int k0 = c * BKC5;
    const int t  = c >> 1;                       // k0 / 256
    const int d0 = (c & 1) << 7;                 // k0 % 256
    const int ts = (t + lag + TNT) & (TNT - 1);
    const int kb = ts * DHD + d0;

    const uint32_t base = sb + buf * BUF5;
    #pragma unroll
    for (int i = 0; i < 16; ++i) {
        int u    = tid + i * 256;                // 0..4095
        int tile = u >> 11;                      // 0..1
        int w    = u & 2047;
        int row  = w >> 4;                       // 0..127
        int seg  = w & 15;                       // 16B segment
        uint32_t dst = base + tile * TILE5 + row * ROW5 + seg * 16;
        const __half* src = (tile == 0)
            ? Ah + (size_t)(bm + row) * KCORR + k0 + seg * 8
            : Ph + (size_t)(bn + row) * KCORR + kb + seg * 8;
        CP_ASYNC_CG_16(dst, src);
    }
    CP_ASYNC_COMMIT();
}

__global__ __launch_bounds__(256, 1)
void corr_hmma_kernel(const __half* __restrict__ Ah,
                      const __half* __restrict__ Ph) {
    const uint32_t sb = smem_u32(dsm);
    const int tid  = threadIdx.x;
    const int wid  = tid >> 5;
    const int lane = tid & 31;
    const int bm = blockIdx.x * 128;
    const int bn = blockIdx.y * 128;
    const int lag = (int)blockIdx.z - MAXLAG;

    const int wm = (wid >> 2) * 64;              // 0, 64
    const int wn = (wid & 3) * 32;               // 0,32,64,96

    float acc[4][4][4];
    #pragma unroll
    for (int mi = 0; mi < 4; ++mi)
        #pragma unroll
        for (int nf = 0; nf < 4; ++nf)
            #pragma unroll
            for (int r = 0; r < 4; ++r) acc[mi][nf][r] = 0.f;

    const int aRow = wm + (lane & 15);
    const int aSeg = (lane >> 4) << 4;
    const int bg   = lane >> 3;
    const int bRow = wn + ((bg >> 1) << 3) + (lane & 7);
    const int bSeg = (bg & 1) << 4;

    // register ks double-buffer
    uint32_t fah[2][4][4], fbh[2][4][2];

    corr_prefetch5(sb, 0, 0, bm, bn, lag, Ah, Ph, tid);

    for (int c = 0; c < NCH5; ++c) {
        const int buf = c & 1;
        if (c + 1 < NCH5) {
            corr_prefetch5(sb, buf ^ 1, c + 1, bm, bn, lag, Ah, Ph, tid);
            CP_ASYNC_WAIT_1();
        } else {
            CP_ASYNC_WAIT_0();
        }
        __syncthreads();

        const uint32_t tb  = sb + buf * BUF5;
        const uint32_t ahB = tb + 0 * TILE5;
        const uint32_t phB = tb + 1 * TILE5;

        // load fragments for ks = 0
        #pragma unroll
        for (int mi = 0; mi < 4; ++mi) {
            uint32_t off = (uint32_t)(aRow + mi * 16) * ROW5 + aSeg;
            LDSM_X4(fah[0][mi], ahB + off);
        }
        #pragma unroll
        for (int ni = 0; ni < 2; ++ni) {
            uint32_t off = (uint32_t)(bRow + ni * 16) * ROW5 + bSeg;
            uint32_t r[4];
            LDSM_X4(r, phB + off);
            fbh[0][2 * ni][0] = r[0]; fbh[0][2 * ni][1] = r[1];
            fbh[0][2 * ni + 1][0] = r[2]; fbh[0][2 * ni + 1][1] = r[3];
        }

        #pragma unroll
        for (int ks = 0; ks < 8; ++ks) {
            const int cur = ks & 1;
            if (ks < 7) {
                const int nxt = cur ^ 1;
                const int kbyte = (ks + 1) * 32;
                #pragma unroll
                for (int mi = 0; mi < 4; ++mi) {
                    uint32_t off = (uint32_t)(aRow + mi * 16) * ROW5 + kbyte + aSeg;
                    LDSM_X4(fah[nxt][mi], ahB + off);
                }
                #pragma unroll
                for (int ni = 0; ni < 2; ++ni) {
                    uint32_t off = (uint32_t)(bRow + ni * 16) * ROW5 + kbyte + bSeg;
                    uint32_t r[4];
                    LDSM_X4(r, phB + off);
                    fbh[nxt][2 * ni][0] = r[0]; fbh[nxt][2 * ni][1] = r[1];
                    fbh[nxt][2 * ni + 1][0] = r[2]; fbh[nxt][2 * ni + 1][1] = r[3];
                }
            }
            #pragma unroll
            for (int mi = 0; mi < 4; ++mi)
                #pragma unroll
                for (int nf = 0; nf < 4; ++nf)
                    mma_f16(acc[mi][nf], fah[cur][mi], fbh[cur][nf]);
        }
        __syncthreads();
    }

    float* Sz = g_S + (size_t)blockIdx.z * QN * CN;
    #pragma unroll
    for (int mi = 0; mi < 4; ++mi) {
        int r0 = bm + wm + mi * 16 + (lane >> 2);
        #pragma unroll
        for (int nf = 0; nf < 4; ++nf) {
            int col = bn + wn + nf * 8 + 2 * (lane & 3);
            float2 v0 = {acc[mi][nf][0], acc[mi][nf][1]};
            float2 v1 = {acc[mi][nf][2], acc[mi][nf][3]};
            *(float2*)&Sz[(size_t)r0 * CN + col]       = v0;
            *(float2*)&Sz[(size_t)(r0 + 8) * CN + col] = v1;
        }
    }
}

// ---------------------------------------------------------------------------
// Final max over lags
// ---------------------------------------------------------------------------
__global__ void maxlag_kernel(float* __restrict__ out) {
    int idx = blockIdx.x * blockDim.x + threadIdx.x;
    float m = g_S[idx];
    #pragma unroll
    for (int j = 1; j < NLAG; ++j)
        m = fmaxf(m, g_S[(size_t)j * QN * CN + idx]);
    out[idx] = m;
}

// ---------------------------------------------------------------------------
// Launch
// ---------------------------------------------------------------------------
extern "C" void kernel_launch(void* const* d_in, const int* in_sizes, int n_in,
                              void* d_out, int out_size) {
    const float* audio = (const float*)d_in[0];
    const float* video = (const float*)d_in[1];
    const float* a_w1  = (const float*)d_in[2];
    const float* a_b1  = (const float*)d_in[3];
    const float* a_w2  = (const float*)d_in[4];
    const float* a_b2  = (const float*)d_in[5];
    const float* v_w1  = (const float*)d_in[6];
    const float* v_b1  = (const float*)d_in[7];
    const float* v_w2  = (const float*)d_in[8];
    const float* v_b2  = (const float*)d_in[9];
    const float* W     = (const float*)d_in[10];
    float* out = (float*)d_out;

    float *gWc, *gbc;
    __half *gHh, *gHl, *gAhf, *gPhf;
    __half *gW1ah, *gW1vh, *gW2ah, *gWcth;
    cudaGetSymbolAddress((void**)&gHh,  g_Hh);
    cudaGetSymbolAddress((void**)&gHl,  g_Hl);
    cudaGetSymbolAddress((void**)&gAhf, g_Ahf);
    cudaGetSymbolAddress((void**)&gPhf, g_Phf);
    cudaGetSymbolAddress((void**)&gWc, g_Wc);
    cudaGetSymbolAddress((void**)&gbc, g_bc);
    cudaGetSymbolAddress((void**)&gW1ah, g_W1ah);
    cudaGetSymbolAddress((void**)&gW1vh, g_W1vh);
    cudaGetSymbolAddress((void**)&gW2ah, g_W2ah);
    cudaGetSymbolAddress((void**)&gWcth, g_Wcth);

    cudaFuncSetAttribute(corr_hmma_kernel,
                         cudaFuncAttributeMaxDynamicSharedMemorySize, CORR_SMEM);
    cudaFuncSetAttribute(mlp_hmma_kernel<true, true, true>,
                         cudaFuncAttributeMaxDynamicSharedMemorySize, HMMA_SMEM);
    cudaFuncSetAttribute(mlp_hmma_kernel<false, false, false>,
                         cudaFuncAttributeMaxDynamicSharedMemorySize, HMMA_SMEM);

    // 0) prep: fold Wc, convert+transpose all weights (fp16 hi)
    prep_w_kernel<<<DHD, DHD>>>(v_w2, v_b2, W);
    convt_kernel<<<DHD, 256>>>(a_w1, gW1ah, DIN);
    convt_kernel<<<DHD, 256>>>(v_w1, gW1vh, DIN);
    convt_kernel<<<DHD, 256>>>(a_w2, gW2ah, DHD);
    convt_kernel<<<DHD, 256>>>(gWc,  gWcth, DHD);

    const dim3 mlp_grid(MROWS / 128, DHD / 128);   // 512 x 2

    // 1) audio MLP on HMMA (2-term)
    mlp_hmma_kernel<true,  true,  true ><<<mlp_grid, 256, HMMA_SMEM>>>(
        audio, nullptr, nullptr, gW1ah, a_b1, gHh, gHl, DIN);
    mlp_hmma_kernel<false, false, false><<<mlp_grid, 256, HMMA_SMEM>>>(
        nullptr, gHh, gHl, gW2ah, a_b2, gAhf, nullptr, DHD);

    // 2) video MLP + folded projection on HMMA (2-term)
    mlp_hmma_kernel<true,  true,  true ><<<mlp_grid, 256, HMMA_SMEM>>>(
        video, nullptr, nullptr, gW1vh, v_b1, gHh, gHl, DIN);
    mlp_hmma_kernel<false, false, false><<<mlp_grid, 256, HMMA_SMEM>>>(
        nullptr, gHh, gHl, gWcth, gbc, gPhf, nullptr, DHD);

    // 3) per-lag correlation: single fp16 term, 144 CTAs, one wave
    corr_hmma_kernel<<<dim3(QN / 128, CN / 128, NLAG), 256, CORR_SMEM>>>(
        gAhf, gPhf);

    // 4) max over lags
    maxlag_kernel<<<(QN * CN) / 256, 256>>>(out);
}

// round 11
// speedup vs baseline: 2.4130x; 1.0807x over previous
#include <cuda_runtime.h>
#include <cuda_fp16.h>
#include <cstdint>

// Problem dims (fixed by the reference)
#define QN   512
#define CN   512
#define TNT  128
#define DIN  512
#define DHD  256
#define KCORR (TNT * DHD)   // 32768
#define MAXLAG 4
#define NLAG  9             // lags -4..4
#define MROWS (QN * TNT)    // 65536

// ---------------------------------------------------------------------------
// Scratch (static device globals; no allocation allowed)
// ---------------------------------------------------------------------------
__device__ __half g_Hh [MROWS * DHD];   // hidden fp16 (reused audio/video)
__device__ __half g_Ahf[MROWS * DHD];   // audio features fp16  [Q, T*DH]
__device__ __half g_Phf[MROWS * DHD];   // projected video fp16 [C, T*DH]
__device__ float g_Wc[DHD * DHD];       // folded v_w2 @ W (fp32)
__device__ float g_bc[DHD];             // folded v_b2 @ W
// pre-converted, pre-transposed weights: [N][K], K contiguous (fp16)
__device__ __half g_W1ah[DHD * DIN];
__device__ __half g_W1vh[DHD * DIN];
__device__ __half g_W2ah[DHD * DHD];
__device__ __half g_Wcth[DHD * DHD];
__device__ float g_S [NLAG * QN * CN];  // per-lag scores

// ---------------------------------------------------------------------------
// Portable PTX helpers (valid on compute_103 virtual target)
// ---------------------------------------------------------------------------
__device__ __forceinline__ uint32_t smem_u32(const void* p) {
    uint32_t a;
    asm("{ .reg .u64 t; cvta.to.shared.u64 t, %1; cvt.u32.u64 %0, t; }"
        : "=r"(a) : "l"(p));
    return a;
}

#define CP_ASYNC_16(dst, src) \
    asm volatile("cp.async.ca.shared.global [%0], [%1], 16;" \
        :: "r"(dst), "l"(src) : "memory")
#define CP_ASYNC_CG_16(dst, src) \
    asm volatile("cp.async.cg.shared.global [%0], [%1], 16;" \
        :: "r"(dst), "l"(src) : "memory")
#define CP_ASYNC_COMMIT() asm volatile("cp.async.commit_group;" ::: "memory")
#define CP_ASYNC_WAIT_1() asm volatile("cp.async.wait_group 1;" ::: "memory")
#define CP_ASYNC_WAIT_0() asm volatile("cp.async.wait_group 0;" ::: "memory")

#define LDSM_X4(r, addr) \
    asm volatile("ldmatrix.sync.aligned.m8n8.x4.shared.b16 {%0,%1,%2,%3}, [%4];" \
        : "=r"((r)[0]), "=r"((r)[1]), "=r"((r)[2]), "=r"((r)[3]) : "r"(addr))

__device__ __forceinline__ void mma_f16(float* c, const uint32_t* a,
                                        const uint32_t* b) {
    asm volatile(
        "mma.sync.aligned.m16n8k16.row.col.f32.f16.f16.f32 "
        "{%0,%1,%2,%3}, {%4,%5,%6,%7}, {%8,%9}, {%0,%1,%2,%3};"
        : "+f"(c[0]), "+f"(c[1]), "+f"(c[2]), "+f"(c[3])
        : "r"(a[0]), "r"(a[1]), "r"(a[2]), "r"(a[3]), "r"(b[0]), "r"(b[1]));
}

// ---------------------------------------------------------------------------
// Prep: fold v_w2 @ W -> g_Wc, g_bc
// ---------------------------------------------------------------------------
__global__ void prep_w_kernel(const float* __restrict__ v_w2,
                              const float* __restrict__ v_b2,
                              const float* __restrict__ W) {
    int i = blockIdx.x;
    int j = threadIdx.x;
    float acc = 0.f;
    #pragma unroll 8
    for (int k = 0; k < DHD; ++k)
        acc += v_w2[i * DHD + k] * W[k * DHD + j];
    g_Wc[i * DHD + j] = acc;
    if (i == 0) {
        float accb = 0.f;
        #pragma unroll 8
        for (int k = 0; k < DHD; ++k)
            accb += v_b2[k] * W[k * DHD + j];
        g_bc[j] = accb;
    }
}

// Prep: transpose + convert fp32 [K, 256] -> fp16 [256][K]
__global__ void convt_kernel(const float* __restrict__ in,
                             __half* __restrict__ oh, int K) {
    int n = blockIdx.x;
    for (int k = threadIdx.x; k < K; k += blockDim.x)
        oh[(size_t)n * K + k] = __float2half_rn(in[(size_t)k * DHD + n]);
}

// ---------------------------------------------------------------------------
// MLP tiling constants (2 tiles: A, B)
// ---------------------------------------------------------------------------
#define BKC     32                  // K elems per chunk (MLP)
#define ROWB    80                  // padded row stride bytes (64 data + 16)
#define TILE_PB (128 * ROWB)        // 10240
#define BUF_PB  (2 * TILE_PB)       // A, B = 20480
#define HMMA_SMEM (2 * BUF_PB)      // 40960

extern __shared__ char dsm[];

// ---------------------------------------------------------------------------
// MLP GEMM on HMMA, pure fp16: O = (relu?)( fp16(A) @ Bh' + bias )
//   layer1 (CONVERT_A=1): fp32 in, converted to fp16 in registers
//   layer2 (CONVERT_A=0): fp16 in from gmem
// 256 threads, 128x128 tile, 8 warps, warp tile 64x32, double-buffered.
// ---------------------------------------------------------------------------
template <bool CONVERT_A, bool RELU>
__global__ __launch_bounds__(256, 1)
void mlp_hmma_kernel(const float* __restrict__ Af,
                     const __half* __restrict__ Ag,
                     const __half* __restrict__ Bh,
                     const float* __restrict__ bias,
                     __half* __restrict__ Oh,
                     int K) {
    const uint32_t sb = smem_u32(dsm);
    const int tid  = threadIdx.x;
    const int wid  = tid >> 5;
    const int lane = tid & 31;
    const int bm = blockIdx.x * 128;
    const int bn = blockIdx.y * 128;
    const int NCH = K / BKC;

    const int wm = (wid >> 2) * 64;
    const int wn = (wid & 3) * 32;

    float acc[4][4][4];
    #pragma unroll
    for (int mi = 0; mi < 4; ++mi)
        #pragma unroll
        for (int nf = 0; nf < 4; ++nf)
            #pragma unroll
            for (int r = 0; r < 4; ++r) acc[mi][nf][r] = 0.f;

    const int aRow = wm + (lane & 15);
    const int aSeg = (lane >> 4) << 4;
    const int bg   = lane >> 3;
    const int bRow = wn + ((bg >> 1) << 3) + (lane & 7);
    const int bSeg = (bg & 1) << 4;

    float4 areg[4];

    auto prefetch_B = [&](int c, int buf) {
        const int k0 = c * BKC;
        const uint32_t base = sb + buf * BUF_PB;
        #pragma unroll
        for (int i = 0; i < 2; ++i) {
            int u = tid + i * 256;               // 0..511
            int row = u >> 2, seg = u & 3;
            uint32_t dst = base + 1 * TILE_PB + row * ROWB + seg * 16;
            const __half* src = Bh + (size_t)(bn + row) * K + k0 + seg * 8;
            CP_ASYNC_16(dst, src);
        }
    };
    auto prefetch_A_f16 = [&](int c, int buf) {
        const int k0 = c * BKC;
        const uint32_t base = sb + buf * BUF_PB;
        #pragma unroll
        for (int i = 0; i < 2; ++i) {
            int u = tid + i * 256;               // 0..511
            int row = u >> 2, seg = u & 3;
            uint32_t dst = base + row * ROWB + seg * 16;
            const __half* src = Ag + (size_t)(bm + row) * K + k0 + seg * 8;
            CP_ASYNC_16(dst, src);
        }
    };
    auto ldg_A_f32 = [&](int c) {
        const int k0 = c * BKC;
        #pragma unroll
        for (int i = 0; i < 4; ++i) {
            int s = tid + i * 256;               // 0..1023
            int row = s >> 3, seg = s & 7;
            areg[i] = *(const float4*)&Af[(size_t)(bm + row) * K + k0 + seg * 4];
        }
    };
    auto sts_A_cvt = [&](int buf) {
        const uint32_t base = sb + buf * BUF_PB;
        #pragma unroll
        for (int i = 0; i < 4; ++i) {
            int s = tid + i * 256;
            int row = s >> 3, seg = s & 7;
            uint32_t off = row * ROWB + seg * 8;
            float4 v = areg[i];
            __half2 h01 = __halves2half2(__float2half_rn(v.x), __float2half_rn(v.y));
            __half2 h23 = __halves2half2(__float2half_rn(v.z), __float2half_rn(v.w));
            uint32_t hu0 = *(uint32_t*)&h01, hu1 = *(uint32_t*)&h23;
            asm volatile("st.shared.v2.b32 [%0], {%1, %2};"
                         :: "r"(base + off), "r"(hu0), "r"(hu1) : "memory");
        }
    };

    if (CONVERT_A) {
        ldg_A_f32(0);
        prefetch_B(0, 0);
        CP_ASYNC_COMMIT();
    } else {
        prefetch_A_f16(0, 0);
        prefetch_B(0, 0);
        CP_ASYNC_COMMIT();
    }

    for (int c = 0; c < NCH; ++c) {
        const int buf = c & 1;
        if (CONVERT_A) {
            sts_A_cvt(buf);
            if (c + 1 < NCH) {
                prefetch_B(c + 1, buf ^ 1);
                CP_ASYNC_COMMIT();
                CP_ASYNC_WAIT_1();
            } else {
                CP_ASYNC_WAIT_0();
            }
            __syncthreads();
            if (c + 1 < NCH) ldg_A_f32(c + 1);
        } else {
            if (c + 1 < NCH) {
                prefetch_A_f16(c + 1, buf ^ 1);
                prefetch_B(c + 1, buf ^ 1);
                CP_ASYNC_COMMIT();
                CP_ASYNC_WAIT_1();
            } else {
                CP_ASYNC_WAIT_0();
            }
            __syncthreads();
        }

        const uint32_t tb  = sb + buf * BUF_PB;
        const uint32_t ahB = tb;
        const uint32_t bhB = tb + 1 * TILE_PB;

        #pragma unroll
        for (int ks = 0; ks < 2; ++ks) {
            const int kbyte = ks * 32;
            uint32_t ah[4][4], ph[4][2];
            #pragma unroll
            for (int mi = 0; mi < 4; ++mi) {
                uint32_t off = (uint32_t)(aRow + mi * 16) * ROWB + kbyte + aSeg;
                LDSM_X4(ah[mi], ahB + off);
            }
            #pragma unroll
            for (int ni = 0; ni < 2; ++ni) {
                uint32_t off = (uint32_t)(bRow + ni * 16) * ROWB + kbyte + bSeg;
                uint32_t r[4];
                LDSM_X4(r, bhB + off);
                ph[2 * ni][0] = r[0]; ph[2 * ni][1] = r[1];
                ph[2 * ni + 1][0] = r[2]; ph[2 * ni + 1][1] = r[3];
            }
            #pragma unroll
            for (int mi = 0; mi < 4; ++mi)
                #pragma unroll
                for (int nf = 0; nf < 4; ++nf)
                    mma_f16(acc[mi][nf], ah[mi], ph[nf]);
        }
        __syncthreads();
    }

    #pragma unroll
    for (int mi = 0; mi < 4; ++mi) {
        int r0 = bm + wm + mi * 16 + (lane >> 2);
        #pragma unroll
        for (int nf = 0; nf < 4; ++nf) {
            int cn = bn + wn + nf * 8 + 2 * (lane & 3);
            float b0 = bias[cn], b1 = bias[cn + 1];
            #pragma unroll
            for (int half_ = 0; half_ < 2; ++half_) {
                int r = r0 + half_ * 8;
                float o0 = acc[mi][nf][2 * half_ + 0] + b0;
                float o1 = acc[mi][nf][2 * half_ + 1] + b1;
                if (RELU) { o0 = fmaxf(o0, 0.f); o1 = fmaxf(o1, 0.f); }
                __half2 hh = __halves2half2(__float2half_rn(o0),
                                            __float2half_rn(o1));
                *(__half2*)&Oh[(size_t)r * DHD + cn] = hh;
            }
        }
    }
}

// ---------------------------------------------------------------------------
// Correlation, v5 (R9/R10-proven): SINGLE fp16 term.
//   128x128 tile, 256 threads, 8 warps, warp tile 64x32, BKC=128 (8 k16
//   steps), register ks double-buffer, 2-stage cp.async. 144 CTAs, one wave.
// ---------------------------------------------------------------------------
#define BKC5     128
#define NCH5     (KCORR / BKC5)      // 256
#define ROW5     272                 // 256B data + 16 pad
#define TILE5    (128 * ROW5)        // 34816
#define BUF5     (2 * TILE5)         // A, P = 69632
#define CORR_SMEM (2 * BUF5)         // 139264

__device__ __forceinline__ void corr_prefetch5(
    uint32_t sb, int buf, int c, int bm, int bn, int lag,
    const __half* __restrict__ Ah, const __half* __restrict__ Ph, int tid)
{
    const int k0 = c * BKC5;
    const int t  = c >> 1;                       // k0 / 256
    const int d0 = (c & 1) << 7;                 // k0 % 256
    const int ts = (t + lag + TNT) & (TNT - 1);
    const int kb = ts * DHD + d0;

    const uint32_t base = sb + buf * BUF5;
    #pragma unroll
    for (int i = 0; i < 16; ++i) {
        int u    = tid + i * 256;                // 0..4095
        int tile = u >> 11;                      // 0..1
        int w    = u & 2047;
        int row  = w >> 4;                       // 0..127
        int seg  = w & 15;                       // 16B segment
        uint32_t dst = base + tile * TILE5 + row * ROW5 + seg * 16;
        const __half* src = (tile == 0)
            ? Ah + (size_t)(bm + row) * KCORR + k0 + seg * 8
            : Ph + (size_t)(bn + row) * KCORR + kb + seg * 8;
        CP_ASYNC_CG_16(dst, src);
    }
    CP_ASYNC_COMMIT();
}

__global__ __launch_bounds__(256, 1)
void corr_hmma_kernel(const __half* __restrict__ Ah,
                      const __half* __restrict__ Ph) {
    const uint32_t sb = smem_u32(dsm);
    const int tid  = threadIdx.x;
    const int wid  = tid >> 5;
    const int lane = tid & 31;
    const int bm = blockIdx.x * 128;
    const int bn = blockIdx.y * 128;
    const int lag = (int)blockIdx.z - MAXLAG;

    const int wm = (wid >> 2) * 64;              // 0, 64
    const int wn = (wid & 3) * 32;               // 0,32,64,96

    float acc[4][4][4];
    #pragma unroll
    for (int mi = 0; mi < 4; ++mi)
        #pragma unroll
        for (int nf = 0; nf < 4; ++nf)
            #pragma unroll
            for (int r = 0; r < 4; ++r) acc[mi][nf][r] = 0.f;

    const int aRow = wm + (lane & 15);
    const int aSeg = (lane >> 4) << 4;
    const int bg   = lane >> 3;
    const int bRow = wn + ((bg >> 1) << 3) + (lane & 7);
    const int bSeg = (bg & 1) << 4;

    // register ks double-buffer
    uint32_t fah[2][4][4], fbh[2][4][2];

    corr_prefetch5(sb, 0, 0, bm, bn, lag, Ah, Ph, tid);

    for (int c = 0; c < NCH5; ++c) {
        const int buf = c & 1;
        if (c + 1 < NCH5) {
            corr_prefetch5(sb, buf ^ 1, c + 1, bm, bn, lag, Ah, Ph, tid);
            CP_ASYNC_WAIT_1();
        } else {
            CP_ASYNC_WAIT_0();
        }
        __syncthreads();

        const uint32_t tb  = sb + buf * BUF5;
        const uint32_t ahB = tb + 0 * TILE5;
        const uint32_t phB = tb + 1 * TILE5;

        // load fragments for ks = 0
        #pragma unroll
        for (int mi = 0; mi < 4; ++mi) {
            uint32_t off = (uint32_t)(aRow + mi * 16) * ROW5 + aSeg;
            LDSM_X4(fah[0][mi], ahB + off);
        }
        #pragma unroll
        for (int ni = 0; ni < 2; ++ni) {
            uint32_t off = (uint32_t)(bRow + ni * 16) * ROW5 + bSeg;
            uint32_t r[4];
            LDSM_X4(r, phB + off);
            fbh[0][2 * ni][0] = r[0]; fbh[0][2 * ni][1] = r[1];
            fbh[0][2 * ni + 1][0] = r[2]; fbh[0][2 * ni + 1][1] = r[3];
        }

        #pragma unroll
        for (int ks = 0; ks < 8; ++ks) {
            const int cur = ks & 1;
            if (ks < 7) {
                const int nxt = cur ^ 1;
                const int kbyte = (ks + 1) * 32;
                #pragma unroll
                for (int mi = 0; mi < 4; ++mi) {
                    uint32_t off = (uint32_t)(aRow + mi * 16) * ROW5 + kbyte + aSeg;
                    LDSM_X4(fah[nxt][mi], ahB + off);
                }
                #pragma unroll
                for (int ni = 0; ni < 2; ++ni) {
                    uint32_t off = (uint32_t)(bRow + ni * 16) * ROW5 + kbyte + bSeg;
                    uint32_t r[4];
                    LDSM_X4(r, phB + off);
                    fbh[nxt][2 * ni][0] = r[0]; fbh[nxt][2 * ni][1] = r[1];
                    fbh[nxt][2 * ni + 1][0] = r[2]; fbh[nxt][2 * ni + 1][1] = r[3];
                }
            }
            #pragma unroll
            for (int mi = 0; mi < 4; ++mi)
                #pragma unroll
                for (int nf = 0; nf < 4; ++nf)
                    mma_f16(acc[mi][nf], fah[cur][mi], fbh[cur][nf]);
        }
        __syncthreads();
    }

    float* Sz = g_S + (size_t)blockIdx.z * QN * CN;
    #pragma unroll
    for (int mi = 0; mi < 4; ++mi) {
        int r0 = bm + wm + mi * 16 + (lane >> 2);
        #pragma unroll
        for (int nf = 0; nf < 4; ++nf) {
            int col = bn + wn + nf * 8 + 2 * (lane & 3);
            float2 v0 = {acc[mi][nf][0], acc[mi][nf][1]};
            float2 v1 = {acc[mi][nf][2], acc[mi][nf][3]};
            *(float2*)&Sz[(size_t)r0 * CN + col]       = v0;
            *(float2*)&Sz[(size_t)(r0 + 8) * CN + col] = v1;
        }
    }
}

// ---------------------------------------------------------------------------
// Final max over lags
// ---------------------------------------------------------------------------
__global__ void maxlag_kernel(float* __restrict__ out) {
    int idx = blockIdx.x * blockDim.x + threadIdx.x;
    float m = g_S[idx];
    #pragma unroll
    for (int j = 1; j < NLAG; ++j)
        m = fmaxf(m, g_S[(size_t)j * QN * CN + idx]);
    out[idx] = m;
}

// ---------------------------------------------------------------------------
// Launch
// ---------------------------------------------------------------------------
extern "C" void kernel_launch(void* const* d_in, const int* in_sizes, int n_in,
                              void* d_out, int out_size) {
    const float* audio = (const float*)d_in[0];
    const float* video = (const float*)d_in[1];
    const float* a_w1  = (const float*)d_in[2];
    const float* a_b1  = (const float*)d_in[3];
    const float* a_w2  = (const float*)d_in[4];
    const float* a_b2  = (const float*)d_in[5];
    const float* v_w1  = (const float*)d_in[6];
    const float* v_b1  = (const float*)d_in[7];
    const float* v_w2  = (const float*)d_in[8];
    const float* v_b2  = (const float*)d_in[9];
    const float* W     = (const float*)d_in[10];
    float* out = (float*)d_out;

    float *gWc, *gbc;
    __half *gHh, *gAhf, *gPhf;
    __half *gW1ah, *gW1vh, *gW2ah, *gWcth;
    cudaGetSymbolAddress((void**)&gHh,  g_Hh);
    cudaGetSymbolAddress((void**)&gAhf, g_Ahf);
    cudaGetSymbolAddress((void**)&gPhf, g_Phf);
    cudaGetSymbolAddress((void**)&gWc, g_Wc);
    cudaGetSymbolAddress((void**)&gbc, g_bc);
    cudaGetSymbolAddress((void**)&gW1ah, g_W1ah);
    cudaGetSymbolAddress((void**)&gW1vh, g_W1vh);
    cudaGetSymbolAddress((void**)&gW2ah, g_W2ah);
    cudaGetSymbolAddress((void**)&gWcth, g_Wcth);

    cudaFuncSetAttribute(corr_hmma_kernel,
                         cudaFuncAttributeMaxDynamicSharedMemorySize, CORR_SMEM);
    cudaFuncSetAttribute(mlp_hmma_kernel<true, true>,
                         cudaFuncAttributeMaxDynamicSharedMemorySize, HMMA_SMEM);
    cudaFuncSetAttribute(mlp_hmma_kernel<false, false>,
                         cudaFuncAttributeMaxDynamicSharedMemorySize, HMMA_SMEM);

    // 0) prep: fold Wc, convert+transpose all weights (fp16)
    prep_w_kernel<<<DHD, DHD>>>(v_w2, v_b2, W);
    convt_kernel<<<DHD, 256>>>(a_w1, gW1ah, DIN);
    convt_kernel<<<DHD, 256>>>(v_w1, gW1vh, DIN);
    convt_kernel<<<DHD, 256>>>(a_w2, gW2ah, DHD);
    convt_kernel<<<DHD, 256>>>(gWc,  gWcth, DHD);

    const dim3 mlp_grid(MROWS / 128, DHD / 128);   // 512 x 2

    // 1) audio MLP on HMMA (pure fp16)
    mlp_hmma_kernel<true,  true ><<<mlp_grid, 256, HMMA_SMEM>>>(
        audio, nullptr, gW1ah, a_b1, gHh, DIN);
    mlp_hmma_kernel<false, false><<<mlp_grid, 256, HMMA_SMEM>>>(
        nullptr, gHh, gW2ah, a_b2, gAhf, DHD);

    // 2) video MLP + folded projection on HMMA (pure fp16)
    mlp_hmma_kernel<true,  true ><<<mlp_grid, 256, HMMA_SMEM>>>(
        video, nullptr, gW1vh, v_b1, gHh, DIN);
    mlp_hmma_kernel<false, false><<<mlp_grid, 256, HMMA_SMEM>>>(
        nullptr, gHh, gWcth, gbc, gPhf, DHD);

    // 3) per-lag correlation: single fp16 term, 144 CTAs, one wave
    corr_hmma_kernel<<<dim3(QN / 128, CN / 128, NLAG), 256, CORR_SMEM>>>(
        gAhf, gPhf);

    // 4) max over lags
    maxlag_kernel<<<(QN * CN) / 256, 256>>>(out);
}